// round 1
// baseline (speedup 1.0000x reference)
#include <cuda_runtime.h>
#include <math.h>

// Problem constants
#define S_LEN 2048
#define HDIM  2048
#define NHQ   16
#define NHKV  4
#define HD    128
#define BATCH 2
#define M_ROWS (BATCH * S_LEN)   // 4096

// Scratch (allocation-free: __device__ globals)
__device__ float g_q[BATCH * NHQ * S_LEN * HD];     // [B,16,S,128]
__device__ float g_k[BATCH * NHKV * S_LEN * HD];    // [B,4,S,128]
__device__ float g_v[BATCH * NHKV * S_LEN * HD];    // [B,4,S,128]
__device__ float g_attn[BATCH * NHQ * S_LEN * HD];  // [B,16,S,128]

// ---------------------------------------------------------------------------
// GEMM: Y = X @ W^T + b, X [4096,2048] row-major, W [N,2048] row-major.
// Output scattered into head-major layout [B, NH, S, 128].
// Tiling: 128x128 block, BK=16, 256 threads, 8x8 per thread.
// ---------------------------------------------------------------------------
__global__ __launch_bounds__(256) void gemm_qkv_kernel(
    const float* __restrict__ X,
    const float* __restrict__ W,
    const float* __restrict__ bias,
    float* __restrict__ out,
    int NH)
{
    __shared__ __align__(16) float As[16][136];
    __shared__ __align__(16) float Bs[16][136];

    const int K  = HDIM;
    const int m0 = blockIdx.y * 128;
    const int n0 = blockIdx.x * 128;
    const int t  = threadIdx.x;
    const int ty = t >> 4;
    const int tx = t & 15;

    float acc[8][8];
#pragma unroll
    for (int i = 0; i < 8; i++)
#pragma unroll
        for (int j = 0; j < 8; j++) acc[i][j] = 0.0f;

    for (int k0 = 0; k0 < K; k0 += 16) {
#pragma unroll
        for (int i = 0; i < 2; i++) {
            int f   = t + i * 256;
            int row = f >> 2;
            int c4  = (f & 3) << 2;
            float4 va = *(const float4*)(X + (size_t)(m0 + row) * K + k0 + c4);
            As[c4 + 0][row] = va.x; As[c4 + 1][row] = va.y;
            As[c4 + 2][row] = va.z; As[c4 + 3][row] = va.w;
            float4 vb = *(const float4*)(W + (size_t)(n0 + row) * K + k0 + c4);
            Bs[c4 + 0][row] = vb.x; Bs[c4 + 1][row] = vb.y;
            Bs[c4 + 2][row] = vb.z; Bs[c4 + 3][row] = vb.w;
        }
        __syncthreads();
#pragma unroll
        for (int kk = 0; kk < 16; kk++) {
            float a[8], b[8];
            *(float4*)(a)     = *(const float4*)&As[kk][ty * 8];
            *(float4*)(a + 4) = *(const float4*)&As[kk][ty * 8 + 4];
            *(float4*)(b)     = *(const float4*)&Bs[kk][tx * 8];
            *(float4*)(b + 4) = *(const float4*)&Bs[kk][tx * 8 + 4];
#pragma unroll
            for (int i = 0; i < 8; i++)
#pragma unroll
                for (int j = 0; j < 8; j++) acc[i][j] += a[i] * b[j];
        }
        __syncthreads();
    }

#pragma unroll
    for (int i = 0; i < 8; i++) {
        int m = m0 + ty * 8 + i;
        int bb = m >> 11;
        int s  = m & 2047;
#pragma unroll
        for (int jv = 0; jv < 2; jv++) {
            int n    = n0 + tx * 8 + jv * 4;
            int head = n >> 7;
            int d    = n & 127;
            float4 bv4 = *(const float4*)(bias + n);
            float4 v;
            v.x = acc[i][jv * 4 + 0] + bv4.x;
            v.y = acc[i][jv * 4 + 1] + bv4.y;
            v.z = acc[i][jv * 4 + 2] + bv4.z;
            v.w = acc[i][jv * 4 + 3] + bv4.w;
            *(float4*)(out + (size_t)(((bb * NH + head) * S_LEN + s) * HD + d)) = v;
        }
    }
}

// ---------------------------------------------------------------------------
// Output projection: Y[m,n] = sum_k attn_gathered[m,k] * wo[n,k]
// attn is [B,16,S,128]; logical k = head*128 + d. Output row-major [4096,2048].
// ---------------------------------------------------------------------------
__global__ __launch_bounds__(256) void gemm_o_kernel(
    const float* __restrict__ A_attn,
    const float* __restrict__ W,
    float* __restrict__ out)
{
    __shared__ __align__(16) float As[16][136];
    __shared__ __align__(16) float Bs[16][136];

    const int K  = HDIM;
    const int m0 = blockIdx.y * 128;
    const int n0 = blockIdx.x * 128;
    const int t  = threadIdx.x;
    const int ty = t >> 4;
    const int tx = t & 15;

    float acc[8][8];
#pragma unroll
    for (int i = 0; i < 8; i++)
#pragma unroll
        for (int j = 0; j < 8; j++) acc[i][j] = 0.0f;

    for (int k0 = 0; k0 < K; k0 += 16) {
#pragma unroll
        for (int i = 0; i < 2; i++) {
            int f   = t + i * 256;
            int row = f >> 2;
            int c4  = (f & 3) << 2;
            int m   = m0 + row;
            int bb  = m >> 11;
            int s   = m & 2047;
            int kg  = k0 + c4;
            int head = kg >> 7;
            int dk   = kg & 127;
            float4 va = *(const float4*)(A_attn +
                (size_t)(((bb * NHQ + head) * S_LEN + s) * HD + dk));
            As[c4 + 0][row] = va.x; As[c4 + 1][row] = va.y;
            As[c4 + 2][row] = va.z; As[c4 + 3][row] = va.w;
            float4 vb = *(const float4*)(W + (size_t)(n0 + row) * K + k0 + c4);
            Bs[c4 + 0][row] = vb.x; Bs[c4 + 1][row] = vb.y;
            Bs[c4 + 2][row] = vb.z; Bs[c4 + 3][row] = vb.w;
        }
        __syncthreads();
#pragma unroll
        for (int kk = 0; kk < 16; kk++) {
            float a[8], b[8];
            *(float4*)(a)     = *(const float4*)&As[kk][ty * 8];
            *(float4*)(a + 4) = *(const float4*)&As[kk][ty * 8 + 4];
            *(float4*)(b)     = *(const float4*)&Bs[kk][tx * 8];
            *(float4*)(b + 4) = *(const float4*)&Bs[kk][tx * 8 + 4];
#pragma unroll
            for (int i = 0; i < 8; i++)
#pragma unroll
                for (int j = 0; j < 8; j++) acc[i][j] += a[i] * b[j];
        }
        __syncthreads();
    }

#pragma unroll
    for (int i = 0; i < 8; i++) {
        int m = m0 + ty * 8 + i;
#pragma unroll
        for (int jv = 0; jv < 2; jv++) {
            int n = n0 + tx * 8 + jv * 4;
            float4 v;
            v.x = acc[i][jv * 4 + 0];
            v.y = acc[i][jv * 4 + 1];
            v.z = acc[i][jv * 4 + 2];
            v.w = acc[i][jv * 4 + 3];
            *(float4*)(out + (size_t)m * HDIM + n) = v;
        }
    }
}

// ---------------------------------------------------------------------------
// RoPE (in place) on [B, NH, S, 128]. One thread per (row, i<64) pair.
// ---------------------------------------------------------------------------
__global__ void rope_kernel(float* __restrict__ buf,
                            const int* __restrict__ pos_ids, int NH)
{
    int idx = blockIdx.x * 256 + threadIdx.x;
    int total = BATCH * NH * S_LEN * 64;
    if (idx >= total) return;
    int i  = idx & 63;
    int s  = (idx >> 6) & 2047;
    int bh = idx >> 17;           // 64*2048 = 2^17
    int b  = bh / NH;

    float p   = (float)pos_ids[b * S_LEN + s];
    // inv_freq = 1e6^(-i/64) = exp(-i * ln(1e6)/64)
    float inv = expf(-(float)i * (13.815510557964274f / 64.0f));
    float ph  = p * inv;
    float c, sn;
    sincosf(ph, &sn, &c);

    size_t base = (size_t)(bh * S_LEN + s) * HD;
    float x1 = buf[base + i];
    float x2 = buf[base + 64 + i];
    buf[base + i]      = x1 * c - x2 * sn;
    buf[base + 64 + i] = x2 * c + x1 * sn;
}

// ---------------------------------------------------------------------------
// Flash attention, fp32, causal, GQA (kv head = h>>2).
// Block = (q-tile 64 rows) x (head) x (batch). 256 threads (16x16).
// Online softmax with shfl-based row stats (rows owned by 16-lane groups).
// ---------------------------------------------------------------------------
#define QS_STR 136
#define KT_STR 68
#define VS_STR 136
#define PS_STR 68
#define FLASH_SMEM_FLOATS (64*QS_STR + 128*KT_STR + 64*VS_STR + 64*PS_STR)
#define FLASH_SMEM_BYTES  (FLASH_SMEM_FLOATS * 4)

__global__ __launch_bounds__(256) void flash_kernel(
    const float* __restrict__ Qg,
    const float* __restrict__ Kg,
    const float* __restrict__ Vg,
    float* __restrict__ Og)
{
    extern __shared__ __align__(16) float sm[];
    float* Qs = sm;                     // [64][136]
    float* Kt = Qs + 64 * QS_STR;       // [128][68]  (transposed K tile)
    float* Vs = Kt + 128 * KT_STR;      // [64][136]
    float* Ps = Vs + 64 * VS_STR;       // [64][68]

    const int iq = blockIdx.x;
    const int h  = blockIdx.y;
    const int b  = blockIdx.z;
    const int hkv = h >> 2;
    const int q0 = iq * 64;
    const int t  = threadIdx.x;
    const int ty = t >> 4;
    const int tx = t & 15;
    const int r0 = ty * 4;
    const int c0 = tx * 4;
    const int cv = tx * 8;
    const float scale = 0.08838834764831845f;   // 1/sqrt(128)

    const float* Qp = Qg + (size_t)((b * NHQ + h) * S_LEN) * HD;
    const float* Kp = Kg + (size_t)((b * NHKV + hkv) * S_LEN) * HD;
    const float* Vp = Vg + (size_t)((b * NHKV + hkv) * S_LEN) * HD;

    // Load Q tile (pre-scaled)
#pragma unroll
    for (int i = 0; i < 8; i++) {
        int f   = t + i * 256;
        int row = f >> 5;
        int c4  = (f & 31) << 2;
        float4 v = *(const float4*)(Qp + (size_t)(q0 + row) * HD + c4);
        v.x *= scale; v.y *= scale; v.z *= scale; v.w *= scale;
        *(float4*)(Qs + row * QS_STR + c4) = v;
    }

    float acc[4][8];
#pragma unroll
    for (int i = 0; i < 4; i++)
#pragma unroll
        for (int j = 0; j < 8; j++) acc[i][j] = 0.0f;
    float m_r[4] = {-1e30f, -1e30f, -1e30f, -1e30f};
    float l_r[4] = {0.0f, 0.0f, 0.0f, 0.0f};

    for (int j = 0; j <= iq; j++) {
        __syncthreads();   // protect Kt/Vs/Ps against previous iteration readers

        // Load K tile transposed (scalar: coalesced gmem, 4-way smem store conflict)
#pragma unroll
        for (int i = 0; i < 32; i++) {
            int idx = t + i * 256;
            int sl  = idx >> 7;
            int d   = idx & 127;
            Kt[d * KT_STR + sl] = Kp[(size_t)(j * 64 + sl) * HD + d];
        }
        // Load V tile (natural layout)
#pragma unroll
        for (int i = 0; i < 8; i++) {
            int f   = t + i * 256;
            int row = f >> 5;
            int c4  = (f & 31) << 2;
            *(float4*)(Vs + row * VS_STR + c4) =
                *(const float4*)(Vp + (size_t)(j * 64 + row) * HD + c4);
        }
        __syncthreads();

        // S = Q K^T (64x64), each thread 4x4
        float sc[4][4];
#pragma unroll
        for (int i = 0; i < 4; i++)
#pragma unroll
            for (int jj = 0; jj < 4; jj++) sc[i][jj] = 0.0f;

#pragma unroll 2
        for (int kk4 = 0; kk4 < 128; kk4 += 4) {
            float qa[4][4];
#pragma unroll
            for (int i = 0; i < 4; i++)
                *(float4*)qa[i] = *(const float4*)(Qs + (r0 + i) * QS_STR + kk4);
#pragma unroll
            for (int u = 0; u < 4; u++) {
                float4 kv = *(const float4*)(Kt + (kk4 + u) * KT_STR + c0);
#pragma unroll
                for (int i = 0; i < 4; i++) {
                    sc[i][0] += qa[i][u] * kv.x;
                    sc[i][1] += qa[i][u] * kv.y;
                    sc[i][2] += qa[i][u] * kv.z;
                    sc[i][3] += qa[i][u] * kv.w;
                }
            }
        }

        // Causal mask on the diagonal tile
        if (j == iq) {
#pragma unroll
            for (int i = 0; i < 4; i++)
#pragma unroll
                for (int jj = 0; jj < 4; jj++)
                    if (c0 + jj > r0 + i) sc[i][jj] = -1e30f;
        }

        // Online softmax: row r owned by the 16 lanes sharing ty (lower/upper
        // half-warp), so xor-shuffles with offset <= 8 stay within the row group.
#pragma unroll
        for (int i = 0; i < 4; i++) {
            float mx = fmaxf(fmaxf(sc[i][0], sc[i][1]), fmaxf(sc[i][2], sc[i][3]));
#pragma unroll
            for (int off = 8; off >= 1; off >>= 1)
                mx = fmaxf(mx, __shfl_xor_sync(0xffffffffu, mx, off));
            float nm = fmaxf(m_r[i], mx);
            float al = __expf(m_r[i] - nm);
            m_r[i] = nm;
            float sum = 0.0f;
#pragma unroll
            for (int jj = 0; jj < 4; jj++) {
                float p = __expf(sc[i][jj] - nm);
                Ps[(r0 + i) * PS_STR + c0 + jj] = p;
                sum += p;
            }
#pragma unroll
            for (int off = 8; off >= 1; off >>= 1)
                sum += __shfl_xor_sync(0xffffffffu, sum, off);
            l_r[i] = l_r[i] * al + sum;
#pragma unroll
            for (int jj = 0; jj < 8; jj++) acc[i][jj] *= al;
        }
        __syncthreads();

        // acc += P @ V  (64x128x64), each thread 4 rows x 8 cols
#pragma unroll 4
        for (int kk = 0; kk < 64; kk++) {
            float4 v0 = *(const float4*)(Vs + kk * VS_STR + cv);
            float4 v1 = *(const float4*)(Vs + kk * VS_STR + cv + 4);
#pragma unroll
            for (int i = 0; i < 4; i++) {
                float p = Ps[(r0 + i) * PS_STR + kk];
                acc[i][0] += p * v0.x; acc[i][1] += p * v0.y;
                acc[i][2] += p * v0.z; acc[i][3] += p * v0.w;
                acc[i][4] += p * v1.x; acc[i][5] += p * v1.y;
                acc[i][6] += p * v1.z; acc[i][7] += p * v1.w;
            }
        }
    }

    // Epilogue: O = acc / l
    float* Op = Og + (size_t)((b * NHQ + h) * S_LEN) * HD;
#pragma unroll
    for (int i = 0; i < 4; i++) {
        float inv_l = 1.0f / l_r[i];
        float4 o0, o1;
        o0.x = acc[i][0] * inv_l; o0.y = acc[i][1] * inv_l;
        o0.z = acc[i][2] * inv_l; o0.w = acc[i][3] * inv_l;
        o1.x = acc[i][4] * inv_l; o1.y = acc[i][5] * inv_l;
        o1.z = acc[i][6] * inv_l; o1.w = acc[i][7] * inv_l;
        *(float4*)(Op + (size_t)(q0 + r0 + i) * HD + cv)     = o0;
        *(float4*)(Op + (size_t)(q0 + r0 + i) * HD + cv + 4) = o1;
    }
}

// ---------------------------------------------------------------------------
// Launch
// ---------------------------------------------------------------------------
extern "C" void kernel_launch(void* const* d_in, const int* in_sizes, int n_in,
                              void* d_out, int out_size)
{
    const float* hs = (const float*)d_in[0];
    const float* wq = (const float*)d_in[1];
    const float* bq = (const float*)d_in[2];
    const float* wk = (const float*)d_in[3];
    const float* bk = (const float*)d_in[4];
    const float* wv = (const float*)d_in[5];
    const float* bv = (const float*)d_in[6];
    const float* wo = (const float*)d_in[7];
    const int*  pos = (const int*)d_in[8];
    float* out = (float*)d_out;

    float *qb, *kb, *vb, *ab;
    cudaGetSymbolAddress((void**)&qb, g_q);
    cudaGetSymbolAddress((void**)&kb, g_k);
    cudaGetSymbolAddress((void**)&vb, g_v);
    cudaGetSymbolAddress((void**)&ab, g_attn);

    cudaFuncSetAttribute(flash_kernel,
                         cudaFuncAttributeMaxDynamicSharedMemorySize,
                         FLASH_SMEM_BYTES);

    // Projections (output in head-major layout)
    gemm_qkv_kernel<<<dim3(HDIM / 128, M_ROWS / 128), 256>>>(hs, wq, bq, qb, NHQ);
    gemm_qkv_kernel<<<dim3((NHKV * HD) / 128, M_ROWS / 128), 256>>>(hs, wk, bk, kb, NHKV);
    gemm_qkv_kernel<<<dim3((NHKV * HD) / 128, M_ROWS / 128), 256>>>(hs, wv, bv, vb, NHKV);

    // RoPE on Q and K
    {
        int total_q = BATCH * NHQ * S_LEN * 64;
        int total_k = BATCH * NHKV * S_LEN * 64;
        rope_kernel<<<(total_q + 255) / 256, 256>>>(qb, pos, NHQ);
        rope_kernel<<<(total_k + 255) / 256, 256>>>(kb, pos, NHKV);
    }

    // Flash attention
    flash_kernel<<<dim3(S_LEN / 64, NHQ, BATCH), 256, FLASH_SMEM_BYTES>>>(qb, kb, vb, ab);

    // Output projection -> d_out
    gemm_o_kernel<<<dim3(HDIM / 128, M_ROWS / 128), 256>>>(ab, wo, out);
}

// round 5
// speedup vs baseline: 1.5846x; 1.5846x over previous
#include <cuda_runtime.h>
#include <cuda_bf16.h>
#include <math.h>
#include <cstdint>

// Problem constants
#define S_LEN 2048
#define HDIM  2048
#define NHQ   16
#define NHKV  4
#define HD    128
#define BATCH 2
#define M_ROWS (BATCH * S_LEN)   // 4096

// ---------------------------------------------------------------------------
// Scratch (allocation-free: __device__ globals)
// ---------------------------------------------------------------------------
__device__ float g_q[BATCH * NHQ * S_LEN * HD];
__device__ float g_k[BATCH * NHKV * S_LEN * HD];
__device__ float g_v[BATCH * NHKV * S_LEN * HD];
__device__ float g_attn[BATCH * NHQ * S_LEN * HD];

__device__ __nv_bfloat16 g_xh[M_ROWS * HDIM];
__device__ __nv_bfloat16 g_xl[M_ROWS * HDIM];
__device__ __nv_bfloat16 g_wqh[HDIM * HDIM];
__device__ __nv_bfloat16 g_wql[HDIM * HDIM];
__device__ __nv_bfloat16 g_wkh[NHKV * HD * HDIM];
__device__ __nv_bfloat16 g_wkl[NHKV * HD * HDIM];
__device__ __nv_bfloat16 g_wvh[NHKV * HD * HDIM];
__device__ __nv_bfloat16 g_wvl[NHKV * HD * HDIM];
__device__ __nv_bfloat16 g_woh[HDIM * HDIM];
__device__ __nv_bfloat16 g_wol[HDIM * HDIM];
__device__ __nv_bfloat16 g_ah[M_ROWS * HDIM];
__device__ __nv_bfloat16 g_al[M_ROWS * HDIM];

// ---------------------------------------------------------------------------
// PTX helpers (portable: mma.sync + ldmatrix + cp.async)
// ---------------------------------------------------------------------------
__device__ __forceinline__ uint32_t smem_to_u32(const void* smem_ptr) {
    uint32_t addr;
    asm("{ .reg .u64 tmp; cvta.to.shared.u64 tmp, %1; cvt.u32.u64 %0, tmp; }"
        : "=r"(addr) : "l"(smem_ptr));
    return addr;
}

__device__ __forceinline__ void ldsm_x4(uint32_t* r, uint32_t addr) {
    asm volatile("ldmatrix.sync.aligned.m8n8.x4.shared.b16 {%0,%1,%2,%3}, [%4];"
                 : "=r"(r[0]), "=r"(r[1]), "=r"(r[2]), "=r"(r[3]) : "r"(addr));
}

__device__ __forceinline__ void mma16816(float* d, const uint32_t* a,
                                         const uint32_t* b) {
    asm volatile(
        "mma.sync.aligned.m16n8k16.row.col.f32.bf16.bf16.f32 "
        "{%0,%1,%2,%3}, {%4,%5,%6,%7}, {%8,%9}, {%0,%1,%2,%3};"
        : "+f"(d[0]), "+f"(d[1]), "+f"(d[2]), "+f"(d[3])
        : "r"(a[0]), "r"(a[1]), "r"(a[2]), "r"(a[3]), "r"(b[0]), "r"(b[1]));
}

#define CP_ASYNC16(dst_u32, src_ptr) \
    asm volatile("cp.async.cg.shared.global [%0], [%1], 16;" \
                 :: "r"(dst_u32), "l"(src_ptr))
#define CP_COMMIT() asm volatile("cp.async.commit_group;" ::: "memory")
#define CP_WAIT(n)  asm volatile("cp.async.wait_group %0;" :: "n"(n) : "memory")

// ---------------------------------------------------------------------------
// fp32 -> bf16 hi/lo split
// ---------------------------------------------------------------------------
__global__ void cvt_split_kernel(const float* __restrict__ in,
                                 __nv_bfloat16* __restrict__ hi,
                                 __nv_bfloat16* __restrict__ lo, int n4)
{
    int i = blockIdx.x * 256 + threadIdx.x;
    if (i >= n4) return;
    float4 v = ((const float4*)in)[i];
    __nv_bfloat16 h0 = __float2bfloat16_rn(v.x);
    __nv_bfloat16 h1 = __float2bfloat16_rn(v.y);
    __nv_bfloat16 h2 = __float2bfloat16_rn(v.z);
    __nv_bfloat16 h3 = __float2bfloat16_rn(v.w);
    __nv_bfloat16 l0 = __float2bfloat16_rn(v.x - __bfloat162float(h0));
    __nv_bfloat16 l1 = __float2bfloat16_rn(v.y - __bfloat162float(h1));
    __nv_bfloat16 l2 = __float2bfloat16_rn(v.z - __bfloat162float(h2));
    __nv_bfloat16 l3 = __float2bfloat16_rn(v.w - __bfloat162float(h3));
    __nv_bfloat162 hp0; hp0.x = h0; hp0.y = h1;
    __nv_bfloat162 hp1; hp1.x = h2; hp1.y = h3;
    __nv_bfloat162 lp0; lp0.x = l0; lp0.y = l1;
    __nv_bfloat162 lp1; lp1.x = l2; lp1.y = l3;
    ((__nv_bfloat162*)hi)[2*i]     = hp0;
    ((__nv_bfloat162*)hi)[2*i + 1] = hp1;
    ((__nv_bfloat162*)lo)[2*i]     = lp0;
    ((__nv_bfloat162*)lo)[2*i + 1] = lp1;
}

// attn [B,16,S,128] -> row-major [m, head*128+d] bf16 hi/lo
__global__ void cvt_attn_kernel(const float* __restrict__ attn,
                                __nv_bfloat16* __restrict__ hi,
                                __nv_bfloat16* __restrict__ lo)
{
    int i = blockIdx.x * 256 + threadIdx.x;
    int n4 = (M_ROWS * HDIM) / 4;
    if (i >= n4) return;
    int o4 = i << 2;
    int k  = o4 & (HDIM - 1);
    int m  = o4 >> 11;
    int b  = m >> 11, s = m & 2047;
    int h  = k >> 7,  d = k & 127;
    float4 v = *(const float4*)(attn + (size_t)(((b * NHQ + h) * S_LEN + s) * HD + d));
    __nv_bfloat16 h0 = __float2bfloat16_rn(v.x);
    __nv_bfloat16 h1 = __float2bfloat16_rn(v.y);
    __nv_bfloat16 h2 = __float2bfloat16_rn(v.z);
    __nv_bfloat16 h3 = __float2bfloat16_rn(v.w);
    __nv_bfloat16 l0 = __float2bfloat16_rn(v.x - __bfloat162float(h0));
    __nv_bfloat16 l1 = __float2bfloat16_rn(v.y - __bfloat162float(h1));
    __nv_bfloat16 l2 = __float2bfloat16_rn(v.z - __bfloat162float(h2));
    __nv_bfloat16 l3 = __float2bfloat16_rn(v.w - __bfloat162float(h3));
    __nv_bfloat162 hp0; hp0.x = h0; hp0.y = h1;
    __nv_bfloat162 hp1; hp1.x = h2; hp1.y = h3;
    __nv_bfloat162 lp0; lp0.x = l0; lp0.y = l1;
    __nv_bfloat162 lp1; lp1.x = l2; lp1.y = l3;
    ((__nv_bfloat162*)hi)[2*i]     = hp0;
    ((__nv_bfloat162*)hi)[2*i + 1] = hp1;
    ((__nv_bfloat162*)lo)[2*i]     = lp0;
    ((__nv_bfloat162*)lo)[2*i + 1] = lp1;
}

// ---------------------------------------------------------------------------
// mma.sync GEMM: D[m,n] = sum_k A[m,k]*B[n,k], bf16 hi/lo (3 MMA terms).
// Block 128x128, BK=32, 8 warps (2x4), warp tile 64x32, cp.async double-buffer.
// Smem rows padded to 40 elements (80B) -> conflict-free ldmatrix.
// ---------------------------------------------------------------------------
#define GSTR 40                      // smem row stride, elements
#define MATB (128 * 80)              // bytes per matrix tile (10240)
#define STAGEB (4 * MATB)            // Ah, Al, Bh, Bl
#define GEMM_SMEM (2 * STAGEB)       // 81920 B

__device__ __forceinline__ void gemm_copy_stage(
    uint32_t s_u32,
    const __nv_bfloat16* __restrict__ Ahp, const __nv_bfloat16* __restrict__ Alp,
    const __nv_bfloat16* __restrict__ Bhp, const __nv_bfloat16* __restrict__ Blp,
    int m0, int n0, int k0, int Kdim, int t)
{
#pragma unroll
    for (int i = 0; i < 2; i++) {
        int chunk = t + i * 256;           // 0..511
        int row = chunk >> 2;
        int ch  = chunk & 3;
        uint32_t dst = s_u32 + row * 80 + ch * 16;
        size_t aoff = (size_t)(m0 + row) * Kdim + k0 + ch * 8;
        size_t boff = (size_t)(n0 + row) * Kdim + k0 + ch * 8;
        CP_ASYNC16(dst,            Ahp + aoff);
        CP_ASYNC16(dst + MATB,     Alp + aoff);
        CP_ASYNC16(dst + 2 * MATB, Bhp + boff);
        CP_ASYNC16(dst + 3 * MATB, Blp + boff);
    }
}

template<int OUT_MODE>
__global__ __launch_bounds__(256) void tc_gemm_kernel(
    const __nv_bfloat16* __restrict__ Ahp, const __nv_bfloat16* __restrict__ Alp,
    const __nv_bfloat16* __restrict__ Bhp, const __nv_bfloat16* __restrict__ Blp,
    const float* __restrict__ bias, float* __restrict__ out,
    int Kdim, int NH)
{
    extern __shared__ char smem[];
    const uint32_t s_u32 = smem_to_u32(smem);
    const int t    = threadIdx.x;
    const int wid  = t >> 5;
    const int lane = t & 31;
    const int m0   = blockIdx.y * 128;
    const int n0   = blockIdx.x * 128;
    const int wm   = (wid >> 2) * 64;    // warp m offset in tile
    const int wn   = (wid & 3) * 32;     // warp n offset in tile

    float acc[4][4][4];                  // [mt][nt][reg]
#pragma unroll
    for (int a = 0; a < 4; a++)
#pragma unroll
        for (int b = 0; b < 4; b++)
#pragma unroll
            for (int c = 0; c < 4; c++) acc[a][b][c] = 0.0f;

    const int nsteps = Kdim >> 5;        // BK=32

    // ldmatrix lane addresses (within a stage base)
    // A: row = wm + mt*16 + (lane&15), col(half kh) = kh*16 + (lane>>4)*8
    const int a_row_l = lane & 15;
    const int a_col_l = (lane >> 4) * 8;
    // B: row = wn + ((lane>>4)<<3) + (lane&7), col = kh*16 + ((lane>>3)&1)*8
    const int b_row_l = ((lane >> 4) << 3) + (lane & 7);
    const int b_col_l = ((lane >> 3) & 1) * 8;

    // Prologue
    gemm_copy_stage(s_u32, Ahp, Alp, Bhp, Blp, m0, n0, 0, Kdim, t);
    CP_COMMIT();

    for (int s = 0; s < nsteps; s++) {
        int buf = s & 1;
        if (s + 1 < nsteps) {
            gemm_copy_stage(s_u32 + (buf ^ 1) * STAGEB, Ahp, Alp, Bhp, Blp,
                            m0, n0, (s + 1) << 5, Kdim, t);
            CP_COMMIT();
            CP_WAIT(1);
        } else {
            CP_WAIT(0);
        }
        __syncthreads();

        uint32_t sA  = s_u32 + buf * STAGEB;
        uint32_t sAl = sA + MATB;
        uint32_t sB  = sA + 2 * MATB;
        uint32_t sBl = sA + 3 * MATB;

#pragma unroll
        for (int kh = 0; kh < 2; kh++) {
            uint32_t ah[4][4], al[4][4], bh[2][4], bl[2][4];
#pragma unroll
            for (int mt = 0; mt < 4; mt++) {
                uint32_t ad = sA + (wm + mt * 16 + a_row_l) * 80 +
                              (kh * 16 + a_col_l) * 2;
                ldsm_x4(ah[mt], ad);
                ldsm_x4(al[mt], ad + MATB);
            }
#pragma unroll
            for (int np = 0; np < 2; np++) {
                uint32_t bd = sB + (wn + np * 16 + b_row_l) * 80 +
                              (kh * 16 + b_col_l) * 2;
                ldsm_x4(bh[np], bd);
                ldsm_x4(bl[np], bd + MATB);
            }
#pragma unroll
            for (int mt = 0; mt < 4; mt++) {
#pragma unroll
                for (int np = 0; np < 2; np++) {
                    mma16816(acc[mt][np * 2],     ah[mt], &bh[np][0]);
                    mma16816(acc[mt][np * 2 + 1], ah[mt], &bh[np][2]);
                    mma16816(acc[mt][np * 2],     ah[mt], &bl[np][0]);
                    mma16816(acc[mt][np * 2 + 1], ah[mt], &bl[np][2]);
                    mma16816(acc[mt][np * 2],     al[mt], &bh[np][0]);
                    mma16816(acc[mt][np * 2 + 1], al[mt], &bh[np][2]);
                }
            }
        }
        __syncthreads();
    }

    // Epilogue. Thread holds D rows (lane>>2, +8), cols (lane&3)*2, +1.
    const int er = lane >> 2;
    const int ec = (lane & 3) * 2;
#pragma unroll
    for (int mt = 0; mt < 4; mt++) {
#pragma unroll
        for (int nt = 0; nt < 4; nt++) {
            int mloc = wm + mt * 16 + er;           // within 128 tile
            int nloc = wn + nt * 8 + ec;
            int m = m0 + mloc;
            float2 v0, v1;
            v0.x = acc[mt][nt][0]; v0.y = acc[mt][nt][1];
            v1.x = acc[mt][nt][2]; v1.y = acc[mt][nt][3];
            if (OUT_MODE == 0) {
                int bb = m >> 11, ss = m & 2047;
                int n = n0 + nloc;
                int head = n >> 7, d = n & 127;
                float bx = bias[n], by = bias[n + 1];
                v0.x += bx; v0.y += by;
                v1.x += bx; v1.y += by;
                float* op = out + (size_t)(((bb * NH + head) * S_LEN + ss) * HD + d);
                *(float2*)op = v0;
                *(float2*)(op + 8 * HD) = v1;
            } else {
                float* op = out + (size_t)m * HDIM + n0 + nloc;
                *(float2*)op = v0;
                *(float2*)(op + 8 * HDIM) = v1;
            }
        }
    }
}

// ---------------------------------------------------------------------------
// RoPE (in place)
// ---------------------------------------------------------------------------
__global__ void rope_kernel(float* __restrict__ buf,
                            const int* __restrict__ pos_ids, int NH)
{
    int idx = blockIdx.x * 256 + threadIdx.x;
    int total = BATCH * NH * S_LEN * 64;
    if (idx >= total) return;
    int i  = idx & 63;
    int s  = (idx >> 6) & 2047;
    int bh = idx >> 17;
    int b  = bh / NH;

    float p   = (float)pos_ids[b * S_LEN + s];
    float inv = expf(-(float)i * (13.815510557964274f / 64.0f));
    float ph  = p * inv;
    float c, sn;
    sincosf(ph, &sn, &c);

    size_t base = (size_t)(bh * S_LEN + s) * HD;
    float x1 = buf[base + i];
    float x2 = buf[base + 64 + i];
    buf[base + i]      = x1 * c - x2 * sn;
    buf[base + 64 + i] = x2 * c + x1 * sn;
}

// ---------------------------------------------------------------------------
// Flash attention (fp32 SIMT, unchanged from R1)
// ---------------------------------------------------------------------------
#define QS_STR 136
#define KT_STR 68
#define VS_STR 136
#define PS_STR 68
#define FLASH_SMEM_FLOATS (64*QS_STR + 128*KT_STR + 64*VS_STR + 64*PS_STR)
#define FLASH_SMEM_BYTES  (FLASH_SMEM_FLOATS * 4)

__global__ __launch_bounds__(256) void flash_kernel(
    const float* __restrict__ Qg,
    const float* __restrict__ Kg,
    const float* __restrict__ Vg,
    float* __restrict__ Og)
{
    extern __shared__ __align__(16) float sm[];
    float* Qs = sm;
    float* Kt = Qs + 64 * QS_STR;
    float* Vs = Kt + 128 * KT_STR;
    float* Ps = Vs + 64 * VS_STR;

    const int iq = blockIdx.x;
    const int h  = blockIdx.y;
    const int b  = blockIdx.z;
    const int hkv = h >> 2;
    const int q0 = iq * 64;
    const int t  = threadIdx.x;
    const int ty = t >> 4;
    const int tx = t & 15;
    const int r0 = ty * 4;
    const int c0 = tx * 4;
    const int cv = tx * 8;
    const float scale = 0.08838834764831845f;

    const float* Qp = Qg + (size_t)((b * NHQ + h) * S_LEN) * HD;
    const float* Kp = Kg + (size_t)((b * NHKV + hkv) * S_LEN) * HD;
    const float* Vp = Vg + (size_t)((b * NHKV + hkv) * S_LEN) * HD;

#pragma unroll
    for (int i = 0; i < 8; i++) {
        int f   = t + i * 256;
        int row = f >> 5;
        int c4  = (f & 31) << 2;
        float4 v = *(const float4*)(Qp + (size_t)(q0 + row) * HD + c4);
        v.x *= scale; v.y *= scale; v.z *= scale; v.w *= scale;
        *(float4*)(Qs + row * QS_STR + c4) = v;
    }

    float acc[4][8];
#pragma unroll
    for (int i = 0; i < 4; i++)
#pragma unroll
        for (int j = 0; j < 8; j++) acc[i][j] = 0.0f;
    float m_r[4] = {-1e30f, -1e30f, -1e30f, -1e30f};
    float l_r[4] = {0.0f, 0.0f, 0.0f, 0.0f};

    for (int j = 0; j <= iq; j++) {
        __syncthreads();
#pragma unroll
        for (int i = 0; i < 32; i++) {
            int idx = t + i * 256;
            int sl  = idx >> 7;
            int d   = idx & 127;
            Kt[d * KT_STR + sl] = Kp[(size_t)(j * 64 + sl) * HD + d];
        }
#pragma unroll
        for (int i = 0; i < 8; i++) {
            int f   = t + i * 256;
            int row = f >> 5;
            int c4  = (f & 31) << 2;
            *(float4*)(Vs + row * VS_STR + c4) =
                *(const float4*)(Vp + (size_t)(j * 64 + row) * HD + c4);
        }
        __syncthreads();

        float sc[4][4];
#pragma unroll
        for (int i = 0; i < 4; i++)
#pragma unroll
            for (int jj = 0; jj < 4; jj++) sc[i][jj] = 0.0f;

#pragma unroll 2
        for (int kk4 = 0; kk4 < 128; kk4 += 4) {
            float qa[4][4];
#pragma unroll
            for (int i = 0; i < 4; i++)
                *(float4*)qa[i] = *(const float4*)(Qs + (r0 + i) * QS_STR + kk4);
#pragma unroll
            for (int u = 0; u < 4; u++) {
                float4 kv = *(const float4*)(Kt + (kk4 + u) * KT_STR + c0);
#pragma unroll
                for (int i = 0; i < 4; i++) {
                    sc[i][0] += qa[i][u] * kv.x;
                    sc[i][1] += qa[i][u] * kv.y;
                    sc[i][2] += qa[i][u] * kv.z;
                    sc[i][3] += qa[i][u] * kv.w;
                }
            }
        }

        if (j == iq) {
#pragma unroll
            for (int i = 0; i < 4; i++)
#pragma unroll
                for (int jj = 0; jj < 4; jj++)
                    if (c0 + jj > r0 + i) sc[i][jj] = -1e30f;
        }

#pragma unroll
        for (int i = 0; i < 4; i++) {
            float mx = fmaxf(fmaxf(sc[i][0], sc[i][1]), fmaxf(sc[i][2], sc[i][3]));
#pragma unroll
            for (int off = 8; off >= 1; off >>= 1)
                mx = fmaxf(mx, __shfl_xor_sync(0xffffffffu, mx, off));
            float nm = fmaxf(m_r[i], mx);
            float al = __expf(m_r[i] - nm);
            m_r[i] = nm;
            float sum = 0.0f;
#pragma unroll
            for (int jj = 0; jj < 4; jj++) {
                float p = __expf(sc[i][jj] - nm);
                Ps[(r0 + i) * PS_STR + c0 + jj] = p;
                sum += p;
            }
#pragma unroll
            for (int off = 8; off >= 1; off >>= 1)
                sum += __shfl_xor_sync(0xffffffffu, sum, off);
            l_r[i] = l_r[i] * al + sum;
#pragma unroll
            for (int jj = 0; jj < 8; jj++) acc[i][jj] *= al;
        }
        __syncthreads();

#pragma unroll 4
        for (int kk = 0; kk < 64; kk++) {
            float4 v0 = *(const float4*)(Vs + kk * VS_STR + cv);
            float4 v1 = *(const float4*)(Vs + kk * VS_STR + cv + 4);
#pragma unroll
            for (int i = 0; i < 4; i++) {
                float p = Ps[(r0 + i) * PS_STR + kk];
                acc[i][0] += p * v0.x; acc[i][1] += p * v0.y;
                acc[i][2] += p * v0.z; acc[i][3] += p * v0.w;
                acc[i][4] += p * v1.x; acc[i][5] += p * v1.y;
                acc[i][6] += p * v1.z; acc[i][7] += p * v1.w;
            }
        }
    }

    float* Op = Og + (size_t)((b * NHQ + h) * S_LEN) * HD;
#pragma unroll
    for (int i = 0; i < 4; i++) {
        float inv_l = 1.0f / l_r[i];
        float4 o0, o1;
        o0.x = acc[i][0] * inv_l; o0.y = acc[i][1] * inv_l;
        o0.z = acc[i][2] * inv_l; o0.w = acc[i][3] * inv_l;
        o1.x = acc[i][4] * inv_l; o1.y = acc[i][5] * inv_l;
        o1.z = acc[i][6] * inv_l; o1.w = acc[i][7] * inv_l;
        *(float4*)(Op + (size_t)(q0 + r0 + i) * HD + cv)     = o0;
        *(float4*)(Op + (size_t)(q0 + r0 + i) * HD + cv + 4) = o1;
    }
}

// ---------------------------------------------------------------------------
// Launch
// ---------------------------------------------------------------------------
extern "C" void kernel_launch(void* const* d_in, const int* in_sizes, int n_in,
                              void* d_out, int out_size)
{
    const float* hs = (const float*)d_in[0];
    const float* wq = (const float*)d_in[1];
    const float* bq = (const float*)d_in[2];
    const float* wk = (const float*)d_in[3];
    const float* bk = (const float*)d_in[4];
    const float* wv = (const float*)d_in[5];
    const float* bv = (const float*)d_in[6];
    const float* wo = (const float*)d_in[7];
    const int*  pos = (const int*)d_in[8];
    float* out = (float*)d_out;

    float *qb, *kb, *vb, *ab;
    cudaGetSymbolAddress((void**)&qb, g_q);
    cudaGetSymbolAddress((void**)&kb, g_k);
    cudaGetSymbolAddress((void**)&vb, g_v);
    cudaGetSymbolAddress((void**)&ab, g_attn);

    __nv_bfloat16 *xh, *xl, *wqh, *wql, *wkh, *wkl, *wvh, *wvl, *woh, *wol, *ah, *al;
    cudaGetSymbolAddress((void**)&xh, g_xh);   cudaGetSymbolAddress((void**)&xl, g_xl);
    cudaGetSymbolAddress((void**)&wqh, g_wqh); cudaGetSymbolAddress((void**)&wql, g_wql);
    cudaGetSymbolAddress((void**)&wkh, g_wkh); cudaGetSymbolAddress((void**)&wkl, g_wkl);
    cudaGetSymbolAddress((void**)&wvh, g_wvh); cudaGetSymbolAddress((void**)&wvl, g_wvl);
    cudaGetSymbolAddress((void**)&woh, g_woh); cudaGetSymbolAddress((void**)&wol, g_wol);
    cudaGetSymbolAddress((void**)&ah, g_ah);   cudaGetSymbolAddress((void**)&al, g_al);

    cudaFuncSetAttribute(flash_kernel,
                         cudaFuncAttributeMaxDynamicSharedMemorySize, FLASH_SMEM_BYTES);
    cudaFuncSetAttribute(tc_gemm_kernel<0>,
                         cudaFuncAttributeMaxDynamicSharedMemorySize, GEMM_SMEM);
    cudaFuncSetAttribute(tc_gemm_kernel<1>,
                         cudaFuncAttributeMaxDynamicSharedMemorySize, GEMM_SMEM);

    // 1. Split inputs into bf16 hi/lo
    {
        int n4x = (M_ROWS * HDIM) / 4;
        cvt_split_kernel<<<(n4x + 255) / 256, 256>>>(hs, xh, xl, n4x);
        int n4q = (HDIM * HDIM) / 4;
        cvt_split_kernel<<<(n4q + 255) / 256, 256>>>(wq, wqh, wql, n4q);
        int n4k = (NHKV * HD * HDIM) / 4;
        cvt_split_kernel<<<(n4k + 255) / 256, 256>>>(wk, wkh, wkl, n4k);
        cvt_split_kernel<<<(n4k + 255) / 256, 256>>>(wv, wvh, wvl, n4k);
        cvt_split_kernel<<<(n4q + 255) / 256, 256>>>(wo, woh, wol, n4q);
    }

    // 2. Projections on tensor cores (head-major output + bias)
    tc_gemm_kernel<0><<<dim3(HDIM / 128, M_ROWS / 128), 256, GEMM_SMEM>>>(
        xh, xl, wqh, wql, bq, qb, HDIM, NHQ);
    tc_gemm_kernel<0><<<dim3((NHKV * HD) / 128, M_ROWS / 128), 256, GEMM_SMEM>>>(
        xh, xl, wkh, wkl, bk, kb, HDIM, NHKV);
    tc_gemm_kernel<0><<<dim3((NHKV * HD) / 128, M_ROWS / 128), 256, GEMM_SMEM>>>(
        xh, xl, wvh, wvl, bv, vb, HDIM, NHKV);

    // 3. RoPE on Q and K
    {
        int total_q = BATCH * NHQ * S_LEN * 64;
        int total_k = BATCH * NHKV * S_LEN * 64;
        rope_kernel<<<(total_q + 255) / 256, 256>>>(qb, pos, NHQ);
        rope_kernel<<<(total_k + 255) / 256, 256>>>(kb, pos, NHKV);
    }

    // 4. Flash attention (fp32)
    flash_kernel<<<dim3(S_LEN / 64, NHQ, BATCH), 256, FLASH_SMEM_BYTES>>>(qb, kb, vb, ab);

    // 5. Split attn output, O-projection on tensor cores (row-major, no bias)
    {
        int n4a = (M_ROWS * HDIM) / 4;
        cvt_attn_kernel<<<(n4a + 255) / 256, 256>>>(ab, ah, al);
    }
    tc_gemm_kernel<1><<<dim3(HDIM / 128, M_ROWS / 128), 256, GEMM_SMEM>>>(
        ah, al, woh, wol, nullptr, out, HDIM, NHQ);
}

// round 6
// speedup vs baseline: 2.1537x; 1.3591x over previous
#include <cuda_runtime.h>
#include <cuda_bf16.h>
#include <math.h>
#include <cstdint>

// Problem constants
#define S_LEN 2048
#define HDIM  2048
#define NHQ   16
#define NHKV  4
#define HD    128
#define BATCH 2
#define M_ROWS (BATCH * S_LEN)   // 4096

// ---------------------------------------------------------------------------
// Scratch (allocation-free: __device__ globals)
// ---------------------------------------------------------------------------
__device__ float g_q[BATCH * NHQ * S_LEN * HD];
__device__ float g_k[BATCH * NHKV * S_LEN * HD];
__device__ float g_v[BATCH * NHKV * S_LEN * HD];
__device__ float g_attn[BATCH * NHQ * S_LEN * HD];

__device__ __nv_bfloat16 g_xh[M_ROWS * HDIM];
__device__ __nv_bfloat16 g_xl[M_ROWS * HDIM];
__device__ __nv_bfloat16 g_wqh[HDIM * HDIM];
__device__ __nv_bfloat16 g_wql[HDIM * HDIM];
__device__ __nv_bfloat16 g_wkh[NHKV * HD * HDIM];
__device__ __nv_bfloat16 g_wkl[NHKV * HD * HDIM];
__device__ __nv_bfloat16 g_wvh[NHKV * HD * HDIM];
__device__ __nv_bfloat16 g_wvl[NHKV * HD * HDIM];
__device__ __nv_bfloat16 g_woh[HDIM * HDIM];
__device__ __nv_bfloat16 g_wol[HDIM * HDIM];
__device__ __nv_bfloat16 g_ah[M_ROWS * HDIM];
__device__ __nv_bfloat16 g_al[M_ROWS * HDIM];

// bf16 hi/lo attention operands
__device__ __nv_bfloat16 g_qh[BATCH * NHQ * S_LEN * HD];
__device__ __nv_bfloat16 g_ql[BATCH * NHQ * S_LEN * HD];
__device__ __nv_bfloat16 g_kh2[BATCH * NHKV * S_LEN * HD];
__device__ __nv_bfloat16 g_kl2[BATCH * NHKV * S_LEN * HD];
__device__ __nv_bfloat16 g_vh2[BATCH * NHKV * S_LEN * HD];
__device__ __nv_bfloat16 g_vl2[BATCH * NHKV * S_LEN * HD];

// ---------------------------------------------------------------------------
// PTX helpers
// ---------------------------------------------------------------------------
__device__ __forceinline__ uint32_t smem_to_u32(const void* smem_ptr) {
    uint32_t addr;
    asm("{ .reg .u64 tmp; cvta.to.shared.u64 tmp, %1; cvt.u32.u64 %0, tmp; }"
        : "=r"(addr) : "l"(smem_ptr));
    return addr;
}

__device__ __forceinline__ void ldsm_x4(uint32_t* r, uint32_t addr) {
    asm volatile("ldmatrix.sync.aligned.m8n8.x4.shared.b16 {%0,%1,%2,%3}, [%4];"
                 : "=r"(r[0]), "=r"(r[1]), "=r"(r[2]), "=r"(r[3]) : "r"(addr));
}

__device__ __forceinline__ void mma16816(float* d, const uint32_t* a,
                                         const uint32_t* b) {
    asm volatile(
        "mma.sync.aligned.m16n8k16.row.col.f32.bf16.bf16.f32 "
        "{%0,%1,%2,%3}, {%4,%5,%6,%7}, {%8,%9}, {%0,%1,%2,%3};"
        : "+f"(d[0]), "+f"(d[1]), "+f"(d[2]), "+f"(d[3])
        : "r"(a[0]), "r"(a[1]), "r"(a[2]), "r"(a[3]), "r"(b[0]), "r"(b[1]));
}

#define CP_ASYNC16(dst_u32, src_ptr) \
    asm volatile("cp.async.cg.shared.global [%0], [%1], 16;" \
                 :: "r"(dst_u32), "l"(src_ptr))
#define CP_COMMIT() asm volatile("cp.async.commit_group;" ::: "memory")
#define CP_WAIT(n)  asm volatile("cp.async.wait_group %0;" :: "n"(n) : "memory")

__device__ __forceinline__ uint32_t pack_bf2(float x, float y) {
    __nv_bfloat162 t = __floats2bfloat162_rn(x, y);
    return *(uint32_t*)&t;
}

// ---------------------------------------------------------------------------
// fp32 -> bf16 hi/lo split
// ---------------------------------------------------------------------------
__global__ void cvt_split_kernel(const float* __restrict__ in,
                                 __nv_bfloat16* __restrict__ hi,
                                 __nv_bfloat16* __restrict__ lo, int n4)
{
    int i = blockIdx.x * 256 + threadIdx.x;
    if (i >= n4) return;
    float4 v = ((const float4*)in)[i];
    __nv_bfloat16 h0 = __float2bfloat16_rn(v.x);
    __nv_bfloat16 h1 = __float2bfloat16_rn(v.y);
    __nv_bfloat16 h2 = __float2bfloat16_rn(v.z);
    __nv_bfloat16 h3 = __float2bfloat16_rn(v.w);
    __nv_bfloat16 l0 = __float2bfloat16_rn(v.x - __bfloat162float(h0));
    __nv_bfloat16 l1 = __float2bfloat16_rn(v.y - __bfloat162float(h1));
    __nv_bfloat16 l2 = __float2bfloat16_rn(v.z - __bfloat162float(h2));
    __nv_bfloat16 l3 = __float2bfloat16_rn(v.w - __bfloat162float(h3));
    __nv_bfloat162 hp0; hp0.x = h0; hp0.y = h1;
    __nv_bfloat162 hp1; hp1.x = h2; hp1.y = h3;
    __nv_bfloat162 lp0; lp0.x = l0; lp0.y = l1;
    __nv_bfloat162 lp1; lp1.x = l2; lp1.y = l3;
    ((__nv_bfloat162*)hi)[2*i]     = hp0;
    ((__nv_bfloat162*)hi)[2*i + 1] = hp1;
    ((__nv_bfloat162*)lo)[2*i]     = lp0;
    ((__nv_bfloat162*)lo)[2*i + 1] = lp1;
}

// attn [B,16,S,128] -> row-major [m, head*128+d] bf16 hi/lo
__global__ void cvt_attn_kernel(const float* __restrict__ attn,
                                __nv_bfloat16* __restrict__ hi,
                                __nv_bfloat16* __restrict__ lo)
{
    int i = blockIdx.x * 256 + threadIdx.x;
    int n4 = (M_ROWS * HDIM) / 4;
    if (i >= n4) return;
    int o4 = i << 2;
    int k  = o4 & (HDIM - 1);
    int m  = o4 >> 11;
    int b  = m >> 11, s = m & 2047;
    int h  = k >> 7,  d = k & 127;
    float4 v = *(const float4*)(attn + (size_t)(((b * NHQ + h) * S_LEN + s) * HD + d));
    __nv_bfloat16 h0 = __float2bfloat16_rn(v.x);
    __nv_bfloat16 h1 = __float2bfloat16_rn(v.y);
    __nv_bfloat16 h2 = __float2bfloat16_rn(v.z);
    __nv_bfloat16 h3 = __float2bfloat16_rn(v.w);
    __nv_bfloat16 l0 = __float2bfloat16_rn(v.x - __bfloat162float(h0));
    __nv_bfloat16 l1 = __float2bfloat16_rn(v.y - __bfloat162float(h1));
    __nv_bfloat16 l2 = __float2bfloat16_rn(v.z - __bfloat162float(h2));
    __nv_bfloat16 l3 = __float2bfloat16_rn(v.w - __bfloat162float(h3));
    __nv_bfloat162 hp0; hp0.x = h0; hp0.y = h1;
    __nv_bfloat162 hp1; hp1.x = h2; hp1.y = h3;
    __nv_bfloat162 lp0; lp0.x = l0; lp0.y = l1;
    __nv_bfloat162 lp1; lp1.x = l2; lp1.y = l3;
    ((__nv_bfloat162*)hi)[2*i]     = hp0;
    ((__nv_bfloat162*)hi)[2*i + 1] = hp1;
    ((__nv_bfloat162*)lo)[2*i]     = lp0;
    ((__nv_bfloat162*)lo)[2*i + 1] = lp1;
}

// ---------------------------------------------------------------------------
// mma.sync GEMM (unchanged from R5)
// ---------------------------------------------------------------------------
#define MATB (128 * 80)
#define STAGEB (4 * MATB)
#define GEMM_SMEM (2 * STAGEB)

__device__ __forceinline__ void gemm_copy_stage(
    uint32_t s_u32,
    const __nv_bfloat16* __restrict__ Ahp, const __nv_bfloat16* __restrict__ Alp,
    const __nv_bfloat16* __restrict__ Bhp, const __nv_bfloat16* __restrict__ Blp,
    int m0, int n0, int k0, int Kdim, int t)
{
#pragma unroll
    for (int i = 0; i < 2; i++) {
        int chunk = t + i * 256;
        int row = chunk >> 2;
        int ch  = chunk & 3;
        uint32_t dst = s_u32 + row * 80 + ch * 16;
        size_t aoff = (size_t)(m0 + row) * Kdim + k0 + ch * 8;
        size_t boff = (size_t)(n0 + row) * Kdim + k0 + ch * 8;
        CP_ASYNC16(dst,            Ahp + aoff);
        CP_ASYNC16(dst + MATB,     Alp + aoff);
        CP_ASYNC16(dst + 2 * MATB, Bhp + boff);
        CP_ASYNC16(dst + 3 * MATB, Blp + boff);
    }
}

template<int OUT_MODE>
__global__ __launch_bounds__(256) void tc_gemm_kernel(
    const __nv_bfloat16* __restrict__ Ahp, const __nv_bfloat16* __restrict__ Alp,
    const __nv_bfloat16* __restrict__ Bhp, const __nv_bfloat16* __restrict__ Blp,
    const float* __restrict__ bias, float* __restrict__ out,
    int Kdim, int NH)
{
    extern __shared__ char smem[];
    const uint32_t s_u32 = smem_to_u32(smem);
    const int t    = threadIdx.x;
    const int wid  = t >> 5;
    const int lane = t & 31;
    const int m0   = blockIdx.y * 128;
    const int n0   = blockIdx.x * 128;
    const int wm   = (wid >> 2) * 64;
    const int wn   = (wid & 3) * 32;

    float acc[4][4][4];
#pragma unroll
    for (int a = 0; a < 4; a++)
#pragma unroll
        for (int b = 0; b < 4; b++)
#pragma unroll
            for (int c = 0; c < 4; c++) acc[a][b][c] = 0.0f;

    const int nsteps = Kdim >> 5;

    const int a_row_l = lane & 15;
    const int a_col_l = (lane >> 4) * 8;
    const int b_row_l = ((lane >> 4) << 3) + (lane & 7);
    const int b_col_l = ((lane >> 3) & 1) * 8;

    gemm_copy_stage(s_u32, Ahp, Alp, Bhp, Blp, m0, n0, 0, Kdim, t);
    CP_COMMIT();

    for (int s = 0; s < nsteps; s++) {
        int buf = s & 1;
        if (s + 1 < nsteps) {
            gemm_copy_stage(s_u32 + (buf ^ 1) * STAGEB, Ahp, Alp, Bhp, Blp,
                            m0, n0, (s + 1) << 5, Kdim, t);
            CP_COMMIT();
            CP_WAIT(1);
        } else {
            CP_WAIT(0);
        }
        __syncthreads();

        uint32_t sA  = s_u32 + buf * STAGEB;
        uint32_t sB  = sA + 2 * MATB;

#pragma unroll
        for (int kh = 0; kh < 2; kh++) {
            uint32_t ah[4][4], al[4][4], bh[2][4], bl[2][4];
#pragma unroll
            for (int mt = 0; mt < 4; mt++) {
                uint32_t ad = sA + (wm + mt * 16 + a_row_l) * 80 +
                              (kh * 16 + a_col_l) * 2;
                ldsm_x4(ah[mt], ad);
                ldsm_x4(al[mt], ad + MATB);
            }
#pragma unroll
            for (int np = 0; np < 2; np++) {
                uint32_t bd = sB + (wn + np * 16 + b_row_l) * 80 +
                              (kh * 16 + b_col_l) * 2;
                ldsm_x4(bh[np], bd);
                ldsm_x4(bl[np], bd + MATB);
            }
#pragma unroll
            for (int mt = 0; mt < 4; mt++) {
#pragma unroll
                for (int np = 0; np < 2; np++) {
                    mma16816(acc[mt][np * 2],     ah[mt], &bh[np][0]);
                    mma16816(acc[mt][np * 2 + 1], ah[mt], &bh[np][2]);
                    mma16816(acc[mt][np * 2],     ah[mt], &bl[np][0]);
                    mma16816(acc[mt][np * 2 + 1], ah[mt], &bl[np][2]);
                    mma16816(acc[mt][np * 2],     al[mt], &bh[np][0]);
                    mma16816(acc[mt][np * 2 + 1], al[mt], &bh[np][2]);
                }
            }
        }
        __syncthreads();
    }

    const int er = lane >> 2;
    const int ec = (lane & 3) * 2;
#pragma unroll
    for (int mt = 0; mt < 4; mt++) {
#pragma unroll
        for (int nt = 0; nt < 4; nt++) {
            int mloc = wm + mt * 16 + er;
            int nloc = wn + nt * 8 + ec;
            int m = m0 + mloc;
            float2 v0, v1;
            v0.x = acc[mt][nt][0]; v0.y = acc[mt][nt][1];
            v1.x = acc[mt][nt][2]; v1.y = acc[mt][nt][3];
            if (OUT_MODE == 0) {
                int bb = m >> 11, ss = m & 2047;
                int n = n0 + nloc;
                int head = n >> 7, d = n & 127;
                float bx = bias[n], by = bias[n + 1];
                v0.x += bx; v0.y += by;
                v1.x += bx; v1.y += by;
                float* op = out + (size_t)(((bb * NH + head) * S_LEN + ss) * HD + d);
                *(float2*)op = v0;
                *(float2*)(op + 8 * HD) = v1;
            } else {
                float* op = out + (size_t)m * HDIM + n0 + nloc;
                *(float2*)op = v0;
                *(float2*)(op + 8 * HDIM) = v1;
            }
        }
    }
}

// ---------------------------------------------------------------------------
// RoPE + bf16 hi/lo split (scale folded in for Q)
// ---------------------------------------------------------------------------
__global__ void rope_split_kernel(const float* __restrict__ buf,
                                  __nv_bfloat16* __restrict__ hi,
                                  __nv_bfloat16* __restrict__ lo,
                                  const int* __restrict__ pos_ids,
                                  int NH, float scale)
{
    int idx = blockIdx.x * 256 + threadIdx.x;
    int total = BATCH * NH * S_LEN * 64;
    if (idx >= total) return;
    int i  = idx & 63;
    int s  = (idx >> 6) & 2047;
    int bh = idx >> 17;            // S_LEN*64 = 2^17
    int b  = bh / NH;

    float p   = (float)pos_ids[b * S_LEN + s];
    float inv = expf(-(float)i * (13.815510557964274f / 64.0f));
    float ph  = p * inv;
    float c, sn;
    sincosf(ph, &sn, &c);

    size_t base = (size_t)(bh * S_LEN + s) * HD;
    float x1 = buf[base + i];
    float x2 = buf[base + 64 + i];
    float y1 = (x1 * c - x2 * sn) * scale;
    float y2 = (x2 * c + x1 * sn) * scale;

    __nv_bfloat16 h1 = __float2bfloat16_rn(y1);
    __nv_bfloat16 h2 = __float2bfloat16_rn(y2);
    hi[base + i]      = h1;
    hi[base + 64 + i] = h2;
    lo[base + i]      = __float2bfloat16_rn(y1 - __bfloat162float(h1));
    lo[base + 64 + i] = __float2bfloat16_rn(y2 - __bfloat162float(h2));
}

// ---------------------------------------------------------------------------
// Tensor-core flash attention, bf16 hi/lo (3-term), causal, GQA.
// BM=128, BN=64. 8 warps; warp w owns q-rows [w*16, w*16+16).
// ---------------------------------------------------------------------------
#define FQ_STR 136
#define FK_STR 136
#define FV_STR 72
#define SQH_OFF 0
#define SQL_OFF (128 * FQ_STR)
#define SKH_OFF (2 * 128 * FQ_STR)
#define SKL_OFF (SKH_OFF + 64 * FK_STR)
#define SVH_OFF (SKL_OFF + 64 * FK_STR)
#define SVL_OFF (SVH_OFF + 128 * FV_STR)
#define FLASH_SMEM_ELEMS (SVL_OFF + 128 * FV_STR)
#define FLASH_SMEM_BYTES (FLASH_SMEM_ELEMS * 2)

__global__ __launch_bounds__(256) void flash_tc_kernel(
    const __nv_bfloat16* __restrict__ Qh_g, const __nv_bfloat16* __restrict__ Ql_g,
    const __nv_bfloat16* __restrict__ Kh_g, const __nv_bfloat16* __restrict__ Kl_g,
    const __nv_bfloat16* __restrict__ Vh_g, const __nv_bfloat16* __restrict__ Vl_g,
    float* __restrict__ Og)
{
    extern __shared__ __align__(16) __nv_bfloat16 sb[];
    const uint32_t s_u32 = smem_to_u32(sb);

    const int iq = blockIdx.x;     // S/128
    const int h  = blockIdx.y;
    const int b  = blockIdx.z;
    const int hkv = h >> 2;
    const int q0 = iq * 128;
    const int t    = threadIdx.x;
    const int wid  = t >> 5;
    const int lane = t & 31;

    const __nv_bfloat16* Qhp = Qh_g + (size_t)((b * NHQ + h) * S_LEN + q0) * HD;
    const __nv_bfloat16* Qlp = Ql_g + (size_t)((b * NHQ + h) * S_LEN + q0) * HD;
    const __nv_bfloat16* Khp = Kh_g + (size_t)((b * NHKV + hkv) * S_LEN) * HD;
    const __nv_bfloat16* Klp = Kl_g + (size_t)((b * NHKV + hkv) * S_LEN) * HD;
    const __nv_bfloat16* Vhp = Vh_g + (size_t)((b * NHKV + hkv) * S_LEN) * HD;
    const __nv_bfloat16* Vlp = Vl_g + (size_t)((b * NHKV + hkv) * S_LEN) * HD;

    // Load Q tile (128 rows x 128 cols, hi+lo)
#pragma unroll
    for (int i = 0; i < 8; i++) {
        int chunk = t + i * 256;           // 0..2047
        int row = chunk >> 4;
        int cg  = chunk & 15;
        uint4 vh = *(const uint4*)(Qhp + (size_t)row * HD + cg * 8);
        uint4 vl = *(const uint4*)(Qlp + (size_t)row * HD + cg * 8);
        *(uint4*)(sb + SQH_OFF + row * FQ_STR + cg * 8) = vh;
        *(uint4*)(sb + SQL_OFF + row * FQ_STR + cg * 8) = vl;
    }

    // Per-thread state
    float o[16][4];
#pragma unroll
    for (int f = 0; f < 16; f++)
#pragma unroll
        for (int e = 0; e < 4; e++) o[f][e] = 0.0f;
    float m0 = -1e30f, m1 = -1e30f, l0 = 0.0f, l1 = 0.0f;

    const int a_row_l = lane & 15;
    const int a_col_l = (lane >> 4) * 8;
    const int b_row_l = ((lane >> 4) << 3) + (lane & 7);
    const int b_col_l = ((lane >> 3) & 1) * 8;
    const int er = lane >> 2;
    const int ec = (lane & 3) * 2;
    const int r0g = q0 + wid * 16 + er;       // global row (upper)
    const int r1g = r0g + 8;

    const int ntiles = (iq + 1) * 2;

    for (int j = 0; j < ntiles; j++) {
        __syncthreads();
        // Load K tile (64 x 128 hi/lo)
#pragma unroll
        for (int i = 0; i < 4; i++) {
            int chunk = t + i * 256;       // 0..1023
            int row = chunk >> 4;
            int cg  = chunk & 15;
            uint4 vh = *(const uint4*)(Khp + (size_t)(j * 64 + row) * HD + cg * 8);
            uint4 vl = *(const uint4*)(Klp + (size_t)(j * 64 + row) * HD + cg * 8);
            *(uint4*)(sb + SKH_OFF + row * FK_STR + cg * 8) = vh;
            *(uint4*)(sb + SKL_OFF + row * FK_STR + cg * 8) = vl;
        }
        // Load V tile transposed: Vt[d][kv]
#pragma unroll
        for (int i = 0; i < 4; i++) {
            int chunk = t + i * 256;
            int row = chunk >> 4;          // kv
            int cg  = chunk & 15;          // d-group of 8
            uint4 vh = *(const uint4*)(Vhp + (size_t)(j * 64 + row) * HD + cg * 8);
            uint4 vl = *(const uint4*)(Vlp + (size_t)(j * 64 + row) * HD + cg * 8);
            __nv_bfloat16 eh[8], el[8];
            *(uint4*)eh = vh; *(uint4*)el = vl;
#pragma unroll
            for (int e = 0; e < 8; e++) {
                sb[SVH_OFF + (cg * 8 + e) * FV_STR + row] = eh[e];
                sb[SVL_OFF + (cg * 8 + e) * FV_STR + row] = el[e];
            }
        }
        __syncthreads();

        // S = Q K^T : c[8 n-frags][4]
        float c[8][4];
#pragma unroll
        for (int nf = 0; nf < 8; nf++)
#pragma unroll
            for (int e = 0; e < 4; e++) c[nf][e] = 0.0f;

#pragma unroll
        for (int kh = 0; kh < 8; kh++) {
            uint32_t ah[4], al[4];
            uint32_t ad = s_u32 + (SQH_OFF + (wid * 16 + a_row_l) * FQ_STR +
                                   kh * 16 + a_col_l) * 2;
            ldsm_x4(ah, ad);
            ldsm_x4(al, ad + SQL_OFF * 2);
#pragma unroll
            for (int np = 0; np < 4; np++) {
                uint32_t bh[4], bl[4];
                uint32_t bd = s_u32 + (SKH_OFF + (np * 16 + b_row_l) * FK_STR +
                                       kh * 16 + b_col_l) * 2;
                ldsm_x4(bh, bd);
                ldsm_x4(bl, bd + (SKL_OFF - SKH_OFF) * 2);
                mma16816(c[np * 2],     ah, &bh[0]);
                mma16816(c[np * 2 + 1], ah, &bh[2]);
                mma16816(c[np * 2],     ah, &bl[0]);
                mma16816(c[np * 2 + 1], ah, &bl[2]);
                mma16816(c[np * 2],     al, &bh[0]);
                mma16816(c[np * 2 + 1], al, &bh[2]);
            }
        }

        // Causal mask (only diagonal-region tiles)
        if (j >= 2 * iq) {
#pragma unroll
            for (int nf = 0; nf < 8; nf++) {
#pragma unroll
                for (int d = 0; d < 2; d++) {
                    int col = j * 64 + nf * 8 + ec + d;
                    if (col > r0g) c[nf][d]     = -1e30f;
                    if (col > r1g) c[nf][2 + d] = -1e30f;
                }
            }
        }

        // Online softmax
        float mx0 = -1e30f, mx1 = -1e30f;
#pragma unroll
        for (int nf = 0; nf < 8; nf++) {
            mx0 = fmaxf(mx0, fmaxf(c[nf][0], c[nf][1]));
            mx1 = fmaxf(mx1, fmaxf(c[nf][2], c[nf][3]));
        }
        mx0 = fmaxf(mx0, __shfl_xor_sync(0xffffffffu, mx0, 1));
        mx0 = fmaxf(mx0, __shfl_xor_sync(0xffffffffu, mx0, 2));
        mx1 = fmaxf(mx1, __shfl_xor_sync(0xffffffffu, mx1, 1));
        mx1 = fmaxf(mx1, __shfl_xor_sync(0xffffffffu, mx1, 2));

        float nm0 = fmaxf(m0, mx0), nm1 = fmaxf(m1, mx1);
        float al0 = __expf(m0 - nm0), al1 = __expf(m1 - nm1);
        m0 = nm0; m1 = nm1;

        float s0 = 0.0f, s1 = 0.0f;
#pragma unroll
        for (int nf = 0; nf < 8; nf++) {
            c[nf][0] = __expf(c[nf][0] - nm0);
            c[nf][1] = __expf(c[nf][1] - nm0);
            c[nf][2] = __expf(c[nf][2] - nm1);
            c[nf][3] = __expf(c[nf][3] - nm1);
            s0 += c[nf][0] + c[nf][1];
            s1 += c[nf][2] + c[nf][3];
        }
        s0 += __shfl_xor_sync(0xffffffffu, s0, 1);
        s0 += __shfl_xor_sync(0xffffffffu, s0, 2);
        s1 += __shfl_xor_sync(0xffffffffu, s1, 1);
        s1 += __shfl_xor_sync(0xffffffffu, s1, 2);
        l0 = l0 * al0 + s0;
        l1 = l1 * al1 + s1;

#pragma unroll
        for (int f = 0; f < 16; f++) {
            o[f][0] *= al0; o[f][1] *= al0;
            o[f][2] *= al1; o[f][3] *= al1;
        }

        // P hi/lo fragments -> PV
#pragma unroll
        for (int kf = 0; kf < 4; kf++) {
            int nf0 = kf * 2, nf1 = kf * 2 + 1;
            float p00 = c[nf0][0], p01 = c[nf0][1], p02 = c[nf0][2], p03 = c[nf0][3];
            float p10 = c[nf1][0], p11 = c[nf1][1], p12 = c[nf1][2], p13 = c[nf1][3];
            uint32_t pah[4], pal[4];
            pah[0] = pack_bf2(p00, p01);
            pah[1] = pack_bf2(p02, p03);
            pah[2] = pack_bf2(p10, p11);
            pah[3] = pack_bf2(p12, p13);
            // residuals
            __nv_bfloat162* hp;
            hp = (__nv_bfloat162*)&pah[0];
            pal[0] = pack_bf2(p00 - __bfloat162float(hp->x), p01 - __bfloat162float(hp->y));
            hp = (__nv_bfloat162*)&pah[1];
            pal[1] = pack_bf2(p02 - __bfloat162float(hp->x), p03 - __bfloat162float(hp->y));
            hp = (__nv_bfloat162*)&pah[2];
            pal[2] = pack_bf2(p10 - __bfloat162float(hp->x), p11 - __bfloat162float(hp->y));
            hp = (__nv_bfloat162*)&pah[3];
            pal[3] = pack_bf2(p12 - __bfloat162float(hp->x), p13 - __bfloat162float(hp->y));

#pragma unroll
            for (int nt = 0; nt < 8; nt++) {
                uint32_t bvh[4], bvl[4];
                uint32_t bd = s_u32 + (SVH_OFF + (nt * 16 + b_row_l) * FV_STR +
                                       kf * 16 + b_col_l) * 2;
                ldsm_x4(bvh, bd);
                ldsm_x4(bvl, bd + (SVL_OFF - SVH_OFF) * 2);
                mma16816(o[nt * 2],     pah, &bvh[0]);
                mma16816(o[nt * 2 + 1], pah, &bvh[2]);
                mma16816(o[nt * 2],     pah, &bvl[0]);
                mma16816(o[nt * 2 + 1], pah, &bvl[2]);
                mma16816(o[nt * 2],     pal, &bvh[0]);
                mma16816(o[nt * 2 + 1], pal, &bvh[2]);
            }
        }
    }

    // Epilogue
    float inv0 = 1.0f / l0, inv1 = 1.0f / l1;
    float* Op0 = Og + (size_t)((b * NHQ + h) * S_LEN + r0g) * HD;
    float* Op1 = Og + (size_t)((b * NHQ + h) * S_LEN + r1g) * HD;
#pragma unroll
    for (int f = 0; f < 16; f++) {
        int col = (f >> 1) * 16 + (f & 1) * 8 + ec;
        float2 v0, v1;
        v0.x = o[f][0] * inv0; v0.y = o[f][1] * inv0;
        v1.x = o[f][2] * inv1; v1.y = o[f][3] * inv1;
        *(float2*)(Op0 + col) = v0;
        *(float2*)(Op1 + col) = v1;
    }
}

// ---------------------------------------------------------------------------
// Launch
// ---------------------------------------------------------------------------
extern "C" void kernel_launch(void* const* d_in, const int* in_sizes, int n_in,
                              void* d_out, int out_size)
{
    const float* hs = (const float*)d_in[0];
    const float* wq = (const float*)d_in[1];
    const float* bq = (const float*)d_in[2];
    const float* wk = (const float*)d_in[3];
    const float* bk = (const float*)d_in[4];
    const float* wv = (const float*)d_in[5];
    const float* bv = (const float*)d_in[6];
    const float* wo = (const float*)d_in[7];
    const int*  pos = (const int*)d_in[8];
    float* out = (float*)d_out;

    float *qb, *kb, *vb, *ab;
    cudaGetSymbolAddress((void**)&qb, g_q);
    cudaGetSymbolAddress((void**)&kb, g_k);
    cudaGetSymbolAddress((void**)&vb, g_v);
    cudaGetSymbolAddress((void**)&ab, g_attn);

    __nv_bfloat16 *xh, *xl, *wqh, *wql, *wkh, *wkl, *wvh, *wvl, *woh, *wol, *ah, *al;
    __nv_bfloat16 *qh, *ql, *kh2, *kl2, *vh2, *vl2;
    cudaGetSymbolAddress((void**)&xh, g_xh);   cudaGetSymbolAddress((void**)&xl, g_xl);
    cudaGetSymbolAddress((void**)&wqh, g_wqh); cudaGetSymbolAddress((void**)&wql, g_wql);
    cudaGetSymbolAddress((void**)&wkh, g_wkh); cudaGetSymbolAddress((void**)&wkl, g_wkl);
    cudaGetSymbolAddress((void**)&wvh, g_wvh); cudaGetSymbolAddress((void**)&wvl, g_wvl);
    cudaGetSymbolAddress((void**)&woh, g_woh); cudaGetSymbolAddress((void**)&wol, g_wol);
    cudaGetSymbolAddress((void**)&ah, g_ah);   cudaGetSymbolAddress((void**)&al, g_al);
    cudaGetSymbolAddress((void**)&qh, g_qh);   cudaGetSymbolAddress((void**)&ql, g_ql);
    cudaGetSymbolAddress((void**)&kh2, g_kh2); cudaGetSymbolAddress((void**)&kl2, g_kl2);
    cudaGetSymbolAddress((void**)&vh2, g_vh2); cudaGetSymbolAddress((void**)&vl2, g_vl2);

    cudaFuncSetAttribute(flash_tc_kernel,
                         cudaFuncAttributeMaxDynamicSharedMemorySize, FLASH_SMEM_BYTES);
    cudaFuncSetAttribute(tc_gemm_kernel<0>,
                         cudaFuncAttributeMaxDynamicSharedMemorySize, GEMM_SMEM);
    cudaFuncSetAttribute(tc_gemm_kernel<1>,
                         cudaFuncAttributeMaxDynamicSharedMemorySize, GEMM_SMEM);

    // 1. Split inputs into bf16 hi/lo
    {
        int n4x = (M_ROWS * HDIM) / 4;
        cvt_split_kernel<<<(n4x + 255) / 256, 256>>>(hs, xh, xl, n4x);
        int n4q = (HDIM * HDIM) / 4;
        cvt_split_kernel<<<(n4q + 255) / 256, 256>>>(wq, wqh, wql, n4q);
        int n4k = (NHKV * HD * HDIM) / 4;
        cvt_split_kernel<<<(n4k + 255) / 256, 256>>>(wk, wkh, wkl, n4k);
        cvt_split_kernel<<<(n4k + 255) / 256, 256>>>(wv, wvh, wvl, n4k);
        cvt_split_kernel<<<(n4q + 255) / 256, 256>>>(wo, woh, wol, n4q);
    }

    // 2. Projections on tensor cores (head-major output + bias)
    tc_gemm_kernel<0><<<dim3(HDIM / 128, M_ROWS / 128), 256, GEMM_SMEM>>>(
        xh, xl, wqh, wql, bq, qb, HDIM, NHQ);
    tc_gemm_kernel<0><<<dim3((NHKV * HD) / 128, M_ROWS / 128), 256, GEMM_SMEM>>>(
        xh, xl, wkh, wkl, bk, kb, HDIM, NHKV);
    tc_gemm_kernel<0><<<dim3((NHKV * HD) / 128, M_ROWS / 128), 256, GEMM_SMEM>>>(
        xh, xl, wvh, wvl, bv, vb, HDIM, NHKV);

    // 3. RoPE + hi/lo split (Q gets 1/sqrt(d) folded in); V plain split
    {
        int total_q = BATCH * NHQ * S_LEN * 64;
        int total_k = BATCH * NHKV * S_LEN * 64;
        rope_split_kernel<<<(total_q + 255) / 256, 256>>>(
            qb, qh, ql, pos, NHQ, 0.08838834764831845f);
        rope_split_kernel<<<(total_k + 255) / 256, 256>>>(
            kb, kh2, kl2, pos, NHKV, 1.0f);
        int n4v = (BATCH * NHKV * S_LEN * HD) / 4;
        cvt_split_kernel<<<(n4v + 255) / 256, 256>>>(vb, vh2, vl2, n4v);
    }

    // 4. Tensor-core flash attention
    flash_tc_kernel<<<dim3(S_LEN / 128, NHQ, BATCH), 256, FLASH_SMEM_BYTES>>>(
        qh, ql, kh2, kl2, vh2, vl2, ab);

    // 5. Split attn output, O-projection on tensor cores
    {
        int n4a = (M_ROWS * HDIM) / 4;
        cvt_attn_kernel<<<(n4a + 255) / 256, 256>>>(ab, ah, al);
    }
    tc_gemm_kernel<1><<<dim3(HDIM / 128, M_ROWS / 128), 256, GEMM_SMEM>>>(
        ah, al, woh, wol, nullptr, out, HDIM, NHQ);
}

// round 7
// speedup vs baseline: 4.6694x; 2.1681x over previous
#include <cuda_runtime.h>
#include <cuda_fp16.h>
#include <math.h>
#include <cstdint>

// Problem constants
#define S_LEN 2048
#define HDIM  2048
#define NHQ   16
#define NHKV  4
#define HD    128
#define BATCH 2
#define M_ROWS (BATCH * S_LEN)   // 4096

// ---------------------------------------------------------------------------
// Scratch (allocation-free: __device__ globals)
// ---------------------------------------------------------------------------
__device__ float g_q[BATCH * NHQ * S_LEN * HD];     // fp32 pre-RoPE Q
__device__ float g_k[BATCH * NHKV * S_LEN * HD];
__device__ float g_v[BATCH * NHKV * S_LEN * HD];

__device__ __half g_x16[M_ROWS * HDIM];             // hidden fp16
__device__ __half g_wq16[HDIM * HDIM];
__device__ __half g_wk16[NHKV * HD * HDIM];
__device__ __half g_wv16[NHKV * HD * HDIM];
__device__ __half g_wo16[HDIM * HDIM];
__device__ __half g_qh16[BATCH * NHQ * S_LEN * HD];   // post-RoPE Q (scaled)
__device__ __half g_kh16[BATCH * NHKV * S_LEN * HD];  // post-RoPE K
__device__ __half g_vh16[BATCH * NHKV * S_LEN * HD];  // V fp16
__device__ __half g_a16[M_ROWS * HDIM];               // attn out, row-major

// ---------------------------------------------------------------------------
// PTX helpers
// ---------------------------------------------------------------------------
__device__ __forceinline__ uint32_t smem_to_u32(const void* smem_ptr) {
    uint32_t addr;
    asm("{ .reg .u64 tmp; cvta.to.shared.u64 tmp, %1; cvt.u32.u64 %0, tmp; }"
        : "=r"(addr) : "l"(smem_ptr));
    return addr;
}

__device__ __forceinline__ void ldsm_x4(uint32_t* r, uint32_t addr) {
    asm volatile("ldmatrix.sync.aligned.m8n8.x4.shared.b16 {%0,%1,%2,%3}, [%4];"
                 : "=r"(r[0]), "=r"(r[1]), "=r"(r[2]), "=r"(r[3]) : "r"(addr));
}

__device__ __forceinline__ void mma16816(float* d, const uint32_t* a,
                                         const uint32_t* b) {
    asm volatile(
        "mma.sync.aligned.m16n8k16.row.col.f32.f16.f16.f32 "
        "{%0,%1,%2,%3}, {%4,%5,%6,%7}, {%8,%9}, {%0,%1,%2,%3};"
        : "+f"(d[0]), "+f"(d[1]), "+f"(d[2]), "+f"(d[3])
        : "r"(a[0]), "r"(a[1]), "r"(a[2]), "r"(a[3]), "r"(b[0]), "r"(b[1]));
}

#define CP_ASYNC16(dst_u32, src_ptr) \
    asm volatile("cp.async.cg.shared.global [%0], [%1], 16;" \
                 :: "r"(dst_u32), "l"(src_ptr))
#define CP_COMMIT() asm volatile("cp.async.commit_group;" ::: "memory")
#define CP_WAIT(n)  asm volatile("cp.async.wait_group %0;" :: "n"(n) : "memory")

__device__ __forceinline__ uint32_t pack_h2(float x, float y) {
    __half2 t = __floats2half2_rn(x, y);
    return *(uint32_t*)&t;
}

// ---------------------------------------------------------------------------
// fp32 -> fp16 convert
// ---------------------------------------------------------------------------
__global__ void cvt_h_kernel(const float* __restrict__ in,
                             __half* __restrict__ out, int n4)
{
    int i = blockIdx.x * 256 + threadIdx.x;
    if (i >= n4) return;
    float4 v = ((const float4*)in)[i];
    __half2 a = __floats2half2_rn(v.x, v.y);
    __half2 b = __floats2half2_rn(v.z, v.w);
    ((__half2*)out)[2 * i]     = a;
    ((__half2*)out)[2 * i + 1] = b;
}

// ---------------------------------------------------------------------------
// fp16 GEMM: D[m,n] = sum_k A[m,k]*B[n,k]; single-term fp16, fp32 accum.
// Block 128x128, BK=32, 8 warps (2x4), warp tile 64x32, cp.async double-buffer.
// ---------------------------------------------------------------------------
#define MATB (128 * 80)              // 10240 B per matrix tile
#define STAGEB (2 * MATB)            // A + B
#define GEMM_SMEM (2 * STAGEB)       // 40960 B

__device__ __forceinline__ void gemm_copy_stage(
    uint32_t s_u32,
    const __half* __restrict__ Ap, const __half* __restrict__ Bp,
    int m0, int n0, int k0, int Kdim, int t)
{
#pragma unroll
    for (int i = 0; i < 2; i++) {
        int chunk = t + i * 256;           // 0..511
        int row = chunk >> 2;
        int ch  = chunk & 3;
        uint32_t dst = s_u32 + row * 80 + ch * 16;
        size_t aoff = (size_t)(m0 + row) * Kdim + k0 + ch * 8;
        size_t boff = (size_t)(n0 + row) * Kdim + k0 + ch * 8;
        CP_ASYNC16(dst,        Ap + aoff);
        CP_ASYNC16(dst + MATB, Bp + boff);
    }
}

template<int OUT_MODE>
__global__ __launch_bounds__(256) void tc_gemm_kernel(
    const __half* __restrict__ Ap, const __half* __restrict__ Bp,
    const float* __restrict__ bias, float* __restrict__ out,
    int Kdim, int NH)
{
    extern __shared__ char smem[];
    const uint32_t s_u32 = smem_to_u32(smem);
    const int t    = threadIdx.x;
    const int wid  = t >> 5;
    const int lane = t & 31;
    const int m0   = blockIdx.y * 128;
    const int n0   = blockIdx.x * 128;
    const int wm   = (wid >> 2) * 64;
    const int wn   = (wid & 3) * 32;

    float acc[4][4][4];
#pragma unroll
    for (int a = 0; a < 4; a++)
#pragma unroll
        for (int b = 0; b < 4; b++)
#pragma unroll
            for (int c = 0; c < 4; c++) acc[a][b][c] = 0.0f;

    const int nsteps = Kdim >> 5;

    const int a_row_l = lane & 15;
    const int a_col_l = (lane >> 4) * 8;
    const int b_row_l = ((lane >> 4) << 3) + (lane & 7);
    const int b_col_l = ((lane >> 3) & 1) * 8;

    gemm_copy_stage(s_u32, Ap, Bp, m0, n0, 0, Kdim, t);
    CP_COMMIT();

    for (int s = 0; s < nsteps; s++) {
        int buf = s & 1;
        if (s + 1 < nsteps) {
            gemm_copy_stage(s_u32 + (buf ^ 1) * STAGEB, Ap, Bp,
                            m0, n0, (s + 1) << 5, Kdim, t);
            CP_COMMIT();
            CP_WAIT(1);
        } else {
            CP_WAIT(0);
        }
        __syncthreads();

        uint32_t sA = s_u32 + buf * STAGEB;
        uint32_t sB = sA + MATB;

#pragma unroll
        for (int kh = 0; kh < 2; kh++) {
            uint32_t ah[4][4], bh[2][4];
#pragma unroll
            for (int mt = 0; mt < 4; mt++) {
                uint32_t ad = sA + (wm + mt * 16 + a_row_l) * 80 +
                              (kh * 16 + a_col_l) * 2;
                ldsm_x4(ah[mt], ad);
            }
#pragma unroll
            for (int np = 0; np < 2; np++) {
                uint32_t bd = sB + (wn + np * 16 + b_row_l) * 80 +
                              (kh * 16 + b_col_l) * 2;
                ldsm_x4(bh[np], bd);
            }
#pragma unroll
            for (int mt = 0; mt < 4; mt++) {
#pragma unroll
                for (int np = 0; np < 2; np++) {
                    mma16816(acc[mt][np * 2],     ah[mt], &bh[np][0]);
                    mma16816(acc[mt][np * 2 + 1], ah[mt], &bh[np][2]);
                }
            }
        }
        __syncthreads();
    }

    const int er = lane >> 2;
    const int ec = (lane & 3) * 2;
#pragma unroll
    for (int mt = 0; mt < 4; mt++) {
#pragma unroll
        for (int nt = 0; nt < 4; nt++) {
            int mloc = wm + mt * 16 + er;
            int nloc = wn + nt * 8 + ec;
            int m = m0 + mloc;
            float2 v0, v1;
            v0.x = acc[mt][nt][0]; v0.y = acc[mt][nt][1];
            v1.x = acc[mt][nt][2]; v1.y = acc[mt][nt][3];
            if (OUT_MODE == 0) {
                int bb = m >> 11, ss = m & 2047;
                int n = n0 + nloc;
                int head = n >> 7, d = n & 127;
                float bx = bias[n], by = bias[n + 1];
                v0.x += bx; v0.y += by;
                v1.x += bx; v1.y += by;
                float* op = out + (size_t)(((bb * NH + head) * S_LEN + ss) * HD + d);
                *(float2*)op = v0;
                *(float2*)(op + 8 * HD) = v1;
            } else {
                float* op = out + (size_t)m * HDIM + n0 + nloc;
                *(float2*)op = v0;
                *(float2*)(op + 8 * HDIM) = v1;
            }
        }
    }
}

// ---------------------------------------------------------------------------
// RoPE -> fp16 (scale folded in)
// ---------------------------------------------------------------------------
__global__ void rope16_kernel(const float* __restrict__ buf,
                              __half* __restrict__ out,
                              const int* __restrict__ pos_ids,
                              int NH, float scale)
{
    int idx = blockIdx.x * 256 + threadIdx.x;
    int total = BATCH * NH * S_LEN * 64;
    if (idx >= total) return;
    int i  = idx & 63;
    int s  = (idx >> 6) & 2047;
    int bh = idx >> 17;
    int b  = bh / NH;

    float p   = (float)pos_ids[b * S_LEN + s];
    float inv = expf(-(float)i * (13.815510557964274f / 64.0f));
    float ph  = p * inv;
    float c, sn;
    sincosf(ph, &sn, &c);

    size_t base = (size_t)(bh * S_LEN + s) * HD;
    float x1 = buf[base + i];
    float x2 = buf[base + 64 + i];
    out[base + i]      = __float2half_rn((x1 * c - x2 * sn) * scale);
    out[base + 64 + i] = __float2half_rn((x2 * c + x1 * sn) * scale);
}

// ---------------------------------------------------------------------------
// Tensor-core flash attention, fp16 single-term, causal, GQA.
// BM=128, BN=64, 8 warps; warp w owns q-rows [w*16, w*16+16).
// Output written as fp16 row-major [m, head*128+d] (A operand of O-proj).
// ---------------------------------------------------------------------------
#define FQ_STR 136
#define FK_STR 136
#define FV_STR 72
#define SQ_OFF 0
#define SK_OFF (128 * FQ_STR)
#define SV_OFF (SK_OFF + 64 * FK_STR)
#define FLASH_SMEM_ELEMS (SV_OFF + 128 * FV_STR)
#define FLASH_SMEM_BYTES (FLASH_SMEM_ELEMS * 2)

__global__ __launch_bounds__(256) void flash16_kernel(
    const __half* __restrict__ Qg, const __half* __restrict__ Kg,
    const __half* __restrict__ Vg, __half* __restrict__ Ag)
{
    extern __shared__ __align__(16) __half sb[];
    const uint32_t s_u32 = smem_to_u32(sb);

    const int iq = blockIdx.x;
    const int h  = blockIdx.y;
    const int b  = blockIdx.z;
    const int hkv = h >> 2;
    const int q0 = iq * 128;
    const int t    = threadIdx.x;
    const int wid  = t >> 5;
    const int lane = t & 31;

    const __half* Qp = Qg + (size_t)((b * NHQ + h) * S_LEN + q0) * HD;
    const __half* Kp = Kg + (size_t)((b * NHKV + hkv) * S_LEN) * HD;
    const __half* Vp = Vg + (size_t)((b * NHKV + hkv) * S_LEN) * HD;

    // Load Q tile (128 x 128)
#pragma unroll
    for (int i = 0; i < 8; i++) {
        int chunk = t + i * 256;
        int row = chunk >> 4;
        int cg  = chunk & 15;
        uint4 v = *(const uint4*)(Qp + (size_t)row * HD + cg * 8);
        *(uint4*)(sb + SQ_OFF + row * FQ_STR + cg * 8) = v;
    }

    float o[16][4];
#pragma unroll
    for (int f = 0; f < 16; f++)
#pragma unroll
        for (int e = 0; e < 4; e++) o[f][e] = 0.0f;
    float m0 = -1e30f, m1 = -1e30f, l0 = 0.0f, l1 = 0.0f;

    const int a_row_l = lane & 15;
    const int a_col_l = (lane >> 4) * 8;
    const int b_row_l = ((lane >> 4) << 3) + (lane & 7);
    const int b_col_l = ((lane >> 3) & 1) * 8;
    const int er = lane >> 2;
    const int ec = (lane & 3) * 2;
    const int r0g = q0 + wid * 16 + er;
    const int r1g = r0g + 8;

    const int ntiles = (iq + 1) * 2;

    for (int j = 0; j < ntiles; j++) {
        __syncthreads();
        // K tile (64 x 128)
#pragma unroll
        for (int i = 0; i < 4; i++) {
            int chunk = t + i * 256;
            int row = chunk >> 4;
            int cg  = chunk & 15;
            uint4 v = *(const uint4*)(Kp + (size_t)(j * 64 + row) * HD + cg * 8);
            *(uint4*)(sb + SK_OFF + row * FK_STR + cg * 8) = v;
        }
        // V tile transposed: Vt[d][kv]
#pragma unroll
        for (int i = 0; i < 4; i++) {
            int chunk = t + i * 256;
            int row = chunk >> 4;          // kv
            int cg  = chunk & 15;          // d-group of 8
            uint4 v = *(const uint4*)(Vp + (size_t)(j * 64 + row) * HD + cg * 8);
            __half e[8];
            *(uint4*)e = v;
#pragma unroll
            for (int u = 0; u < 8; u++)
                sb[SV_OFF + (cg * 8 + u) * FV_STR + row] = e[u];
        }
        __syncthreads();

        // S = Q K^T
        float c[8][4];
#pragma unroll
        for (int nf = 0; nf < 8; nf++)
#pragma unroll
            for (int e = 0; e < 4; e++) c[nf][e] = 0.0f;

#pragma unroll
        for (int kh = 0; kh < 8; kh++) {
            uint32_t ah[4];
            uint32_t ad = s_u32 + (SQ_OFF + (wid * 16 + a_row_l) * FQ_STR +
                                   kh * 16 + a_col_l) * 2;
            ldsm_x4(ah, ad);
#pragma unroll
            for (int np = 0; np < 4; np++) {
                uint32_t bh[4];
                uint32_t bd = s_u32 + (SK_OFF + (np * 16 + b_row_l) * FK_STR +
                                       kh * 16 + b_col_l) * 2;
                ldsm_x4(bh, bd);
                mma16816(c[np * 2],     ah, &bh[0]);
                mma16816(c[np * 2 + 1], ah, &bh[2]);
            }
        }

        // Causal mask
        if (j >= 2 * iq) {
#pragma unroll
            for (int nf = 0; nf < 8; nf++) {
#pragma unroll
                for (int d = 0; d < 2; d++) {
                    int col = j * 64 + nf * 8 + ec + d;
                    if (col > r0g) c[nf][d]     = -1e30f;
                    if (col > r1g) c[nf][2 + d] = -1e30f;
                }
            }
        }

        // Online softmax
        float mx0 = -1e30f, mx1 = -1e30f;
#pragma unroll
        for (int nf = 0; nf < 8; nf++) {
            mx0 = fmaxf(mx0, fmaxf(c[nf][0], c[nf][1]));
            mx1 = fmaxf(mx1, fmaxf(c[nf][2], c[nf][3]));
        }
        mx0 = fmaxf(mx0, __shfl_xor_sync(0xffffffffu, mx0, 1));
        mx0 = fmaxf(mx0, __shfl_xor_sync(0xffffffffu, mx0, 2));
        mx1 = fmaxf(mx1, __shfl_xor_sync(0xffffffffu, mx1, 1));
        mx1 = fmaxf(mx1, __shfl_xor_sync(0xffffffffu, mx1, 2));

        float nm0 = fmaxf(m0, mx0), nm1 = fmaxf(m1, mx1);
        float al0 = __expf(m0 - nm0), al1 = __expf(m1 - nm1);
        m0 = nm0; m1 = nm1;

        float s0 = 0.0f, s1 = 0.0f;
#pragma unroll
        for (int nf = 0; nf < 8; nf++) {
            c[nf][0] = __expf(c[nf][0] - nm0);
            c[nf][1] = __expf(c[nf][1] - nm0);
            c[nf][2] = __expf(c[nf][2] - nm1);
            c[nf][3] = __expf(c[nf][3] - nm1);
            s0 += c[nf][0] + c[nf][1];
            s1 += c[nf][2] + c[nf][3];
        }
        s0 += __shfl_xor_sync(0xffffffffu, s0, 1);
        s0 += __shfl_xor_sync(0xffffffffu, s0, 2);
        s1 += __shfl_xor_sync(0xffffffffu, s1, 1);
        s1 += __shfl_xor_sync(0xffffffffu, s1, 2);
        l0 = l0 * al0 + s0;
        l1 = l1 * al1 + s1;

#pragma unroll
        for (int f = 0; f < 16; f++) {
            o[f][0] *= al0; o[f][1] *= al0;
            o[f][2] *= al1; o[f][3] *= al1;
        }

        // P fragments -> PV
#pragma unroll
        for (int kf = 0; kf < 4; kf++) {
            int nf0 = kf * 2, nf1 = kf * 2 + 1;
            uint32_t pa[4];
            pa[0] = pack_h2(c[nf0][0], c[nf0][1]);
            pa[1] = pack_h2(c[nf0][2], c[nf0][3]);
            pa[2] = pack_h2(c[nf1][0], c[nf1][1]);
            pa[3] = pack_h2(c[nf1][2], c[nf1][3]);
#pragma unroll
            for (int nt = 0; nt < 8; nt++) {
                uint32_t bv[4];
                uint32_t bd = s_u32 + (SV_OFF + (nt * 16 + b_row_l) * FV_STR +
                                       kf * 16 + b_col_l) * 2;
                ldsm_x4(bv, bd);
                mma16816(o[nt * 2],     pa, &bv[0]);
                mma16816(o[nt * 2 + 1], pa, &bv[2]);
            }
        }
    }

    // Epilogue: fp16 row-major [m, h*128 + d]
    float inv0 = 1.0f / l0, inv1 = 1.0f / l1;
    __half* Ap0 = Ag + (size_t)(b * S_LEN + r0g) * HDIM + h * HD;
    __half* Ap1 = Ag + (size_t)(b * S_LEN + r1g) * HDIM + h * HD;
#pragma unroll
    for (int f = 0; f < 16; f++) {
        int col = (f >> 1) * 16 + (f & 1) * 8 + ec;
        __half2 v0 = __floats2half2_rn(o[f][0] * inv0, o[f][1] * inv0);
        __half2 v1 = __floats2half2_rn(o[f][2] * inv1, o[f][3] * inv1);
        *(__half2*)(Ap0 + col) = v0;
        *(__half2*)(Ap1 + col) = v1;
    }
}

// ---------------------------------------------------------------------------
// Launch
// ---------------------------------------------------------------------------
extern "C" void kernel_launch(void* const* d_in, const int* in_sizes, int n_in,
                              void* d_out, int out_size)
{
    const float* hs = (const float*)d_in[0];
    const float* wq = (const float*)d_in[1];
    const float* bq = (const float*)d_in[2];
    const float* wk = (const float*)d_in[3];
    const float* bk = (const float*)d_in[4];
    const float* wv = (const float*)d_in[5];
    const float* bv = (const float*)d_in[6];
    const float* wo = (const float*)d_in[7];
    const int*  pos = (const int*)d_in[8];
    float* out = (float*)d_out;

    float *qb, *kb, *vb;
    cudaGetSymbolAddress((void**)&qb, g_q);
    cudaGetSymbolAddress((void**)&kb, g_k);
    cudaGetSymbolAddress((void**)&vb, g_v);

    __half *x16, *wq16, *wk16, *wv16, *wo16, *qh16, *kh16, *vh16, *a16;
    cudaGetSymbolAddress((void**)&x16,  g_x16);
    cudaGetSymbolAddress((void**)&wq16, g_wq16);
    cudaGetSymbolAddress((void**)&wk16, g_wk16);
    cudaGetSymbolAddress((void**)&wv16, g_wv16);
    cudaGetSymbolAddress((void**)&wo16, g_wo16);
    cudaGetSymbolAddress((void**)&qh16, g_qh16);
    cudaGetSymbolAddress((void**)&kh16, g_kh16);
    cudaGetSymbolAddress((void**)&vh16, g_vh16);
    cudaGetSymbolAddress((void**)&a16,  g_a16);

    cudaFuncSetAttribute(flash16_kernel,
                         cudaFuncAttributeMaxDynamicSharedMemorySize, FLASH_SMEM_BYTES);
    cudaFuncSetAttribute(tc_gemm_kernel<0>,
                         cudaFuncAttributeMaxDynamicSharedMemorySize, GEMM_SMEM);
    cudaFuncSetAttribute(tc_gemm_kernel<1>,
                         cudaFuncAttributeMaxDynamicSharedMemorySize, GEMM_SMEM);

    // 1. Convert inputs to fp16
    {
        int n4x = (M_ROWS * HDIM) / 4;
        cvt_h_kernel<<<(n4x + 255) / 256, 256>>>(hs, x16, n4x);
        int n4q = (HDIM * HDIM) / 4;
        cvt_h_kernel<<<(n4q + 255) / 256, 256>>>(wq, wq16, n4q);
        int n4k = (NHKV * HD * HDIM) / 4;
        cvt_h_kernel<<<(n4k + 255) / 256, 256>>>(wk, wk16, n4k);
        cvt_h_kernel<<<(n4k + 255) / 256, 256>>>(wv, wv16, n4k);
        cvt_h_kernel<<<(n4q + 255) / 256, 256>>>(wo, wo16, n4q);
    }

    // 2. Projections (head-major fp32 output + bias)
    tc_gemm_kernel<0><<<dim3(HDIM / 128, M_ROWS / 128), 256, GEMM_SMEM>>>(
        x16, wq16, bq, qb, HDIM, NHQ);
    tc_gemm_kernel<0><<<dim3((NHKV * HD) / 128, M_ROWS / 128), 256, GEMM_SMEM>>>(
        x16, wk16, bk, kb, HDIM, NHKV);
    tc_gemm_kernel<0><<<dim3((NHKV * HD) / 128, M_ROWS / 128), 256, GEMM_SMEM>>>(
        x16, wv16, bv, vb, HDIM, NHKV);

    // 3. RoPE -> fp16 (Q scaled by 1/sqrt(d)); V fp32 -> fp16
    {
        int total_q = BATCH * NHQ * S_LEN * 64;
        int total_k = BATCH * NHKV * S_LEN * 64;
        rope16_kernel<<<(total_q + 255) / 256, 256>>>(
            qb, qh16, pos, NHQ, 0.08838834764831845f);
        rope16_kernel<<<(total_k + 255) / 256, 256>>>(
            kb, kh16, pos, NHKV, 1.0f);
        int n4v = (BATCH * NHKV * S_LEN * HD) / 4;
        cvt_h_kernel<<<(n4v + 255) / 256, 256>>>(vb, vh16, n4v);
    }

    // 4. Flash attention (fp16 MMA), writes fp16 row-major attn directly
    flash16_kernel<<<dim3(S_LEN / 128, NHQ, BATCH), 256, FLASH_SMEM_BYTES>>>(
        qh16, kh16, vh16, a16);

    // 5. O-projection -> d_out (row-major fp32)
    tc_gemm_kernel<1><<<dim3(HDIM / 128, M_ROWS / 128), 256, GEMM_SMEM>>>(
        a16, wo16, nullptr, out, HDIM, NHQ);
}